// round 6
// baseline (speedup 1.0000x reference)
#include <cuda_runtime.h>
#include <cuda_bf16.h>
#include <math.h>
#include <stdint.h>

typedef __nv_bfloat16 bf;

// Problem constants
#define Bn   4
#define Sn   4096
#define Dn   1024
#define Mn   128
#define Cn   128
#define NCn  (Sn / Cn)
#define BSn  (Bn * Sn)
#define DECAYF 0.99f
#define LRF    0.01f

// Scratch (device globals)
__device__ bf    g_kh[BSn * Mn], g_kl[BSn * Mn];
__device__ bf    g_vh[BSn * Mn], g_vl[BSn * Mn];
__device__ bf    g_qh[BSn * Mn], g_ql[BSn * Mn];
__device__ bf    g_Sh[Bn * NCn * Mn * Mn], g_Sl[Bn * NCn * Mn * Mn];
__device__ bf    g_Wh[4 * 128 * 1024], g_Wl[4 * 128 * 1024];  // Wk,Wv,Wq,Wo
__device__ float g_att[BSn * Mn];
__device__ float g_dS [Bn * NCn * Mn * Mn];

// ===========================================================================
// helpers
// ===========================================================================
__device__ __forceinline__ uint32_t smem_u32(const void* p) {
    uint32_t a;
    asm("{ .reg .u64 t; cvta.to.shared.u64 t, %1; cvt.u32.u64 %0, t; }"
        : "=r"(a) : "l"(p));
    return a;
}
__device__ __forceinline__ void splitf(float v, bf& h, bf& l) {
    h = __float2bfloat16(v);
    l = __float2bfloat16(v - __bfloat162float(h));
}
__device__ __forceinline__ uint32_t pack2(bf a, bf b) {
    __nv_bfloat162 t; t.x = a; t.y = b;
    return *(uint32_t*)&t;
}
__device__ __forceinline__ void mma_bf16(float* d, const uint32_t* a, const uint32_t* b) {
    asm volatile(
        "mma.sync.aligned.m16n8k16.row.col.f32.bf16.bf16.f32 "
        "{%0,%1,%2,%3}, {%4,%5,%6,%7}, {%8,%9}, {%0,%1,%2,%3};"
        : "+f"(d[0]), "+f"(d[1]), "+f"(d[2]), "+f"(d[3])
        : "r"(a[0]), "r"(a[1]), "r"(a[2]), "r"(a[3]), "r"(b[0]), "r"(b[1]));
}
#define CPASYNC16(sa, gp) \
    asm volatile("cp.async.ca.shared.global [%0], [%1], 16;" :: "r"(sa), "l"(gp))
#define CPCOMMIT() asm volatile("cp.async.commit_group;")
#define CPWAIT2()  asm volatile("cp.async.wait_group 2;")

extern __shared__ float sm_dyn[];

// ===========================================================================
// conv_w: weights -> bf16 hi/lo planes.  Wk|Wv|Wq|Wo at offsets 0..3 *131072
// ===========================================================================
__global__ void __launch_bounds__(256) conv_w_kernel(
    const float* __restrict__ Wk, const float* __restrict__ Wv,
    const float* __restrict__ Wq, const float* __restrict__ Wo)
{
    const int i = blockIdx.x * 256 + threadIdx.x;   // < 524288
    float v;
    if (i < 131072)       v = Wk[i];
    else if (i < 262144)  v = Wv[i - 131072];
    else if (i < 393216)  v = Wq[i - 262144];
    else                  v = Wo[i - 393216];
    bf h, l; splitf(v, h, l);
    g_Wh[i] = h; g_Wl[i] = l;
}

// ===========================================================================
// Mixed GEMM: A fp32 (register-prefetch split), B bf16 planes (cp.async 4-stage)
// C[128,128] = A[128,K] * B^T (+bias). 256 thr, 8 warps 4x2, warp 32x64, Kc=16.
// smem 73728 B: sAh[2][3072] sAl[2][3072] sBh[4][3072] sBl[4][3072], stride 24.
// EPI: 0 = fp32 C + bias, 1 = bf16 plane outputs + bias.
// ===========================================================================
#define SROW 24
#define STG  3072

template<int EPI>
__device__ __forceinline__ void gemm_mixed(
    const float* __restrict__ A, int lda,
    const bf* __restrict__ Bh, const bf* __restrict__ Bl, int ldb, int K,
    const float* __restrict__ bias,
    float* __restrict__ Cf, bf* __restrict__ Ch, bf* __restrict__ Cl, int ldc)
{
    bf* sAh = (bf*)sm_dyn;
    bf* sAl = sAh + 2 * STG;
    bf* sBh = sAl + 2 * STG;
    bf* sBl = sBh + 4 * STG;
    const uint32_t uBh = smem_u32(sBh), uBl = smem_u32(sBl);

    const int tid = threadIdx.x;
    const int lane = tid & 31, wid = tid >> 5;
    const int wm = wid >> 1, wn = wid & 1;
    const int g = lane >> 2, t4 = lane & 3;
    const int row = tid >> 1, half = tid & 1;

    float acc[2][8][4];
#pragma unroll
    for (int mt = 0; mt < 2; mt++)
#pragma unroll
        for (int nt = 0; nt < 8; nt++)
#pragma unroll
            for (int r = 0; r < 4; r++) acc[mt][nt][r] = 0.f;

    const int nc = K >> 4;

#define ISSUE_B(ch) do { \
    const uint32_t _d = (((ch) & 3) * STG + row * SROW + half * 8) * 2; \
    const size_t _s = (size_t)row * ldb + (ch) * 16 + half * 8; \
    CPASYNC16(uBh + _d, Bh + _s); \
    CPASYNC16(uBl + _d, Bl + _s); \
} while (0)

    ISSUE_B(0); CPCOMMIT();
    ISSUE_B(1); CPCOMMIT();
    ISSUE_B(2); CPCOMMIT();

    float pre[8];
    {
        const float* ap = A + (size_t)row * lda + half * 8;
        float4 a0 = *(const float4*)ap, a1 = *(const float4*)(ap + 4);
        pre[0]=a0.x; pre[1]=a0.y; pre[2]=a0.z; pre[3]=a0.w;
        pre[4]=a1.x; pre[5]=a1.y; pre[6]=a1.z; pre[7]=a1.w;
    }

    for (int ch = 0; ch < nc; ch++) {
        // split+store A chunk
        {
            uint32_t hw[4], lw[4];
#pragma unroll
            for (int j = 0; j < 4; j++) {
                bf h0, l0, h1, l1;
                splitf(pre[2*j],   h0, l0);
                splitf(pre[2*j+1], h1, l1);
                hw[j] = pack2(h0, h1);
                lw[j] = pack2(l0, l1);
            }
            const int off = (ch & 1) * STG + row * SROW + half * 8;
            *(uint4*)(sAh + off) = *(uint4*)hw;
            *(uint4*)(sAl + off) = *(uint4*)lw;
        }
        if (ch + 1 < nc) {
            const float* ap = A + (size_t)row * lda + (ch + 1) * 16 + half * 8;
            float4 a0 = *(const float4*)ap, a1 = *(const float4*)(ap + 4);
            pre[0]=a0.x; pre[1]=a0.y; pre[2]=a0.z; pre[3]=a0.w;
            pre[4]=a1.x; pre[5]=a1.y; pre[6]=a1.z; pre[7]=a1.w;
        }
        CPWAIT2();
        __syncthreads();
        if (ch + 3 < nc) ISSUE_B(ch + 3);
        CPCOMMIT();

        const bf* pAh = sAh + (ch & 1) * STG;
        const bf* pAl = sAl + (ch & 1) * STG;
        const bf* pBh = sBh + (ch & 3) * STG;
        const bf* pBl = sBl + (ch & 3) * STG;

        uint32_t ah[2][4], al[2][4];
#pragma unroll
        for (int mt = 0; mt < 2; mt++) {
            const int br = wm * 32 + mt * 16;
            ah[mt][0] = *(const uint32_t*)(pAh + (br + g    ) * SROW + 2 * t4);
            ah[mt][1] = *(const uint32_t*)(pAh + (br + g + 8) * SROW + 2 * t4);
            ah[mt][2] = *(const uint32_t*)(pAh + (br + g    ) * SROW + 2 * t4 + 8);
            ah[mt][3] = *(const uint32_t*)(pAh + (br + g + 8) * SROW + 2 * t4 + 8);
            al[mt][0] = *(const uint32_t*)(pAl + (br + g    ) * SROW + 2 * t4);
            al[mt][1] = *(const uint32_t*)(pAl + (br + g + 8) * SROW + 2 * t4);
            al[mt][2] = *(const uint32_t*)(pAl + (br + g    ) * SROW + 2 * t4 + 8);
            al[mt][3] = *(const uint32_t*)(pAl + (br + g + 8) * SROW + 2 * t4 + 8);
        }
#pragma unroll
        for (int nt = 0; nt < 8; nt++) {
            const int bn = wn * 64 + nt * 8 + g;
            uint32_t bh[2], bl[2];
            bh[0] = *(const uint32_t*)(pBh + bn * SROW + 2 * t4);
            bh[1] = *(const uint32_t*)(pBh + bn * SROW + 2 * t4 + 8);
            bl[0] = *(const uint32_t*)(pBl + bn * SROW + 2 * t4);
            bl[1] = *(const uint32_t*)(pBl + bn * SROW + 2 * t4 + 8);
#pragma unroll
            for (int mt = 0; mt < 2; mt++) {
                mma_bf16(acc[mt][nt], ah[mt], bh);
                mma_bf16(acc[mt][nt], al[mt], bh);
                mma_bf16(acc[mt][nt], ah[mt], bl);
            }
        }
    }
#undef ISSUE_B

#pragma unroll
    for (int mt = 0; mt < 2; mt++) {
        const int r0 = wm * 32 + mt * 16 + g;
#pragma unroll
        for (int nt = 0; nt < 8; nt++) {
            const int c0 = wn * 64 + nt * 8 + 2 * t4;
            const float b0 = bias ? bias[c0] : 0.f;
            const float b1 = bias ? bias[c0 + 1] : 0.f;
            float v00 = acc[mt][nt][0] + b0, v01 = acc[mt][nt][1] + b1;
            float v10 = acc[mt][nt][2] + b0, v11 = acc[mt][nt][3] + b1;
            if (EPI == 0) {
                *(float2*)(Cf + (size_t)r0 * ldc + c0)       = make_float2(v00, v01);
                *(float2*)(Cf + (size_t)(r0 + 8) * ldc + c0) = make_float2(v10, v11);
            } else {
                bf h0,l0,h1,l1;
                splitf(v00, h0, l0); splitf(v01, h1, l1);
                *(uint32_t*)(Ch + (size_t)r0 * ldc + c0) = pack2(h0, h1);
                *(uint32_t*)(Cl + (size_t)r0 * ldc + c0) = pack2(l0, l1);
                splitf(v10, h0, l0); splitf(v11, h1, l1);
                *(uint32_t*)(Ch + (size_t)(r0 + 8) * ldc + c0) = pack2(h0, h1);
                *(uint32_t*)(Cl + (size_t)(r0 + 8) * ldc + c0) = pack2(l0, l1);
            }
        }
    }
}

// ===========================================================================
// K1: projections -> plane outputs   grid (128, 3)
// ===========================================================================
__global__ void __launch_bounds__(256, 2) proj_kernel(
    const float* __restrict__ x,
    const float* __restrict__ bk, const float* __restrict__ bv,
    const float* __restrict__ bq)
{
    const size_t rb = (size_t)blockIdx.x * 128;
    const int y = blockIdx.y;
    const float* bias = (y == 0) ? bk : (y == 1) ? bv : bq;
    bf* Ch = (y == 0) ? g_kh : (y == 1) ? g_vh : g_qh;
    bf* Cl = (y == 0) ? g_kl : (y == 1) ? g_vl : g_ql;
    gemm_mixed<1>(x + rb * Dn, Dn,
                  g_Wh + (size_t)y * 131072, g_Wl + (size_t)y * 131072, Dn, Dn,
                  bias, nullptr, Ch + rb * Mn, Cl + rb * Mn, Mn);
}

// ===========================================================================
// K5: y = att @ Wo^T + bo   grid (128, 8)
// ===========================================================================
__global__ void __launch_bounds__(256, 2) outproj_kernel(
    const float* __restrict__ bo, float* __restrict__ y)
{
    const size_t rb = (size_t)blockIdx.x * 128;
    const int    cb = blockIdx.y * 128;
    gemm_mixed<0>(g_att + rb * Mn, Mn,
                  g_Wh + 393216 + (size_t)cb * Mn, g_Wl + 393216 + (size_t)cb * Mn, Mn, Mn,
                  bo + cb, y + rb * Dn + cb, nullptr, nullptr, Dn);
}

// ===========================================================================
// K4: inter — att[t][i] += decay^t * sum_j S[i][j] q[t][j]
// A = q planes, B = S planes, both cp.async 4-stage. grid 128.
// smem 98304 B: sAh[4][3072] sAl[4] sBh[4] sBl[4]
// ===========================================================================
__global__ void __launch_bounds__(256) inter_kernel()
{
    bf* sAh = (bf*)sm_dyn;
    bf* sAl = sAh + 4 * STG;
    bf* sBh = sAl + 4 * STG;
    bf* sBl = sBh + 4 * STG;
    const uint32_t uAh = smem_u32(sAh), uAl = smem_u32(sAl);
    const uint32_t uBh = smem_u32(sBh), uBl = smem_u32(sBl);

    const int tid = threadIdx.x;
    const int lane = tid & 31, wid = tid >> 5;
    const int wm = wid >> 1, wn = wid & 1;
    const int g = lane >> 2, t4 = lane & 3;
    const int row = tid >> 1, half = tid & 1;

    const int b = blockIdx.x / NCn;
    const int c = blockIdx.x % NCn;
    const size_t base  = ((size_t)b * Sn + (size_t)c * Cn) * Mn;
    const size_t sbase = ((size_t)b * NCn + c) * 16384;

    const bf* Ah = g_qh + base; const bf* Al = g_ql + base;
    const bf* Bh = g_Sh + sbase; const bf* Bl = g_Sl + sbase;

    float acc[2][8][4];
#pragma unroll
    for (int mt = 0; mt < 2; mt++)
#pragma unroll
        for (int nt = 0; nt < 8; nt++)
#pragma unroll
            for (int r = 0; r < 4; r++) acc[mt][nt][r] = 0.f;

#define ISSUE2(ch) do { \
    const uint32_t _d = (((ch) & 3) * STG + row * SROW + half * 8) * 2; \
    const size_t _s = (size_t)row * Mn + (ch) * 16 + half * 8; \
    CPASYNC16(uAh + _d, Ah + _s); \
    CPASYNC16(uAl + _d, Al + _s); \
    CPASYNC16(uBh + _d, Bh + _s); \
    CPASYNC16(uBl + _d, Bl + _s); \
} while (0)

    ISSUE2(0); CPCOMMIT();
    ISSUE2(1); CPCOMMIT();
    ISSUE2(2); CPCOMMIT();

    for (int ch = 0; ch < 8; ch++) {
        CPWAIT2();
        __syncthreads();
        if (ch + 3 < 8) ISSUE2(ch + 3);
        CPCOMMIT();

        const bf* pAh = sAh + (ch & 3) * STG;
        const bf* pAl = sAl + (ch & 3) * STG;
        const bf* pBh = sBh + (ch & 3) * STG;
        const bf* pBl = sBl + (ch & 3) * STG;

        uint32_t ah[2][4], al[2][4];
#pragma unroll
        for (int mt = 0; mt < 2; mt++) {
            const int br = wm * 32 + mt * 16;
            ah[mt][0] = *(const uint32_t*)(pAh + (br + g    ) * SROW + 2 * t4);
            ah[mt][1] = *(const uint32_t*)(pAh + (br + g + 8) * SROW + 2 * t4);
            ah[mt][2] = *(const uint32_t*)(pAh + (br + g    ) * SROW + 2 * t4 + 8);
            ah[mt][3] = *(const uint32_t*)(pAh + (br + g + 8) * SROW + 2 * t4 + 8);
            al[mt][0] = *(const uint32_t*)(pAl + (br + g    ) * SROW + 2 * t4);
            al[mt][1] = *(const uint32_t*)(pAl + (br + g + 8) * SROW + 2 * t4);
            al[mt][2] = *(const uint32_t*)(pAl + (br + g    ) * SROW + 2 * t4 + 8);
            al[mt][3] = *(const uint32_t*)(pAl + (br + g + 8) * SROW + 2 * t4 + 8);
        }
#pragma unroll
        for (int nt = 0; nt < 8; nt++) {
            const int bn = wn * 64 + nt * 8 + g;
            uint32_t bh[2], bl[2];
            bh[0] = *(const uint32_t*)(pBh + bn * SROW + 2 * t4);
            bh[1] = *(const uint32_t*)(pBh + bn * SROW + 2 * t4 + 8);
            bl[0] = *(const uint32_t*)(pBl + bn * SROW + 2 * t4);
            bl[1] = *(const uint32_t*)(pBl + bn * SROW + 2 * t4 + 8);
#pragma unroll
            for (int mt = 0; mt < 2; mt++) {
                mma_bf16(acc[mt][nt], ah[mt], bh);
                mma_bf16(acc[mt][nt], al[mt], bh);
                mma_bf16(acc[mt][nt], ah[mt], bl);
            }
        }
    }
#undef ISSUE2

#pragma unroll
    for (int mt = 0; mt < 2; mt++) {
        const int r0 = wm * 32 + mt * 16 + g;
        const float f0 = powf(DECAYF, (float)r0);
        const float f1 = powf(DECAYF, (float)(r0 + 8));
#pragma unroll
        for (int nt = 0; nt < 8; nt++) {
            const int c0 = wn * 64 + nt * 8 + 2 * t4;
            float2* p0 = (float2*)(g_att + base + (size_t)r0 * Mn + c0);
            float2* p1 = (float2*)(g_att + base + (size_t)(r0 + 8) * Mn + c0);
            float2 o0 = *p0, o1 = *p1;
            o0.x += f0 * acc[mt][nt][0]; o0.y += f0 * acc[mt][nt][1];
            o1.x += f1 * acc[mt][nt][2]; o1.y += f1 * acc[mt][nt][3];
            *p0 = o0; *p1 = o1;
        }
    }
}

// ===========================================================================
// K2: chunk — three 128^3 GEMMs on resident smem planes. grid 128, 256 thr.
// smem: 6 planes of 128x136 bf16 (Q|S , K , Vt each hi+lo) + dpow. 209408 B.
// ===========================================================================
#define CP 136
#define CPL (128 * CP)

__device__ __forceinline__ void gemm_sm_bf16(
    const bf* __restrict__ Ah, const bf* __restrict__ Al,
    const bf* __restrict__ Bh, const bf* __restrict__ Bl,
    float acc[2][8][4], int wm, int wn, int g, int t4)
{
#pragma unroll
    for (int kk = 0; kk < 8; kk++) {
        const int ko = kk * 16;
        uint32_t ah[2][4], al[2][4];
#pragma unroll
        for (int mt = 0; mt < 2; mt++) {
            const int br = wm * 32 + mt * 16;
            ah[mt][0] = *(const uint32_t*)(Ah + (br + g    ) * CP + ko + 2 * t4);
            ah[mt][1] = *(const uint32_t*)(Ah + (br + g + 8) * CP + ko + 2 * t4);
            ah[mt][2] = *(const uint32_t*)(Ah + (br + g    ) * CP + ko + 2 * t4 + 8);
            ah[mt][3] = *(const uint32_t*)(Ah + (br + g + 8) * CP + ko + 2 * t4 + 8);
            al[mt][0] = *(const uint32_t*)(Al + (br + g    ) * CP + ko + 2 * t4);
            al[mt][1] = *(const uint32_t*)(Al + (br + g + 8) * CP + ko + 2 * t4);
            al[mt][2] = *(const uint32_t*)(Al + (br + g    ) * CP + ko + 2 * t4 + 8);
            al[mt][3] = *(const uint32_t*)(Al + (br + g + 8) * CP + ko + 2 * t4 + 8);
        }
#pragma unroll
        for (int nt = 0; nt < 8; nt++) {
            const int bn = wn * 64 + nt * 8 + g;
            uint32_t bh[2], bl[2];
            bh[0] = *(const uint32_t*)(Bh + bn * CP + ko + 2 * t4);
            bh[1] = *(const uint32_t*)(Bh + bn * CP + ko + 2 * t4 + 8);
            bl[0] = *(const uint32_t*)(Bl + bn * CP + ko + 2 * t4);
            bl[1] = *(const uint32_t*)(Bl + bn * CP + ko + 2 * t4 + 8);
#pragma unroll
            for (int mt = 0; mt < 2; mt++) {
                mma_bf16(acc[mt][nt], ah[mt], bh);
                mma_bf16(acc[mt][nt], al[mt], bh);
                mma_bf16(acc[mt][nt], ah[mt], bl);
            }
        }
    }
}

__global__ void __launch_bounds__(256) chunk_kernel()
{
    bf* Qh  = (bf*)sm_dyn;          // -> S planes -> Ktw planes
    bf* Ql  = Qh + CPL;
    bf* Kh  = Qh + 2 * CPL;
    bf* Kl  = Qh + 3 * CPL;
    bf* Vth = Qh + 4 * CPL;
    bf* Vtl = Qh + 5 * CPL;
    float* dpow = (float*)(Qh + 6 * CPL);

    const uint32_t uQh = smem_u32(Qh);
    const int tid = threadIdx.x;
    const int lane = tid & 31, wid = tid >> 5;
    const int wm = wid >> 1, wn = wid & 1;
    const int g = lane >> 2, t4 = lane & 3;
    const int b = blockIdx.x / NCn;
    const int c = blockIdx.x % NCn;
    const size_t base = ((size_t)b * Sn + (size_t)c * Cn) * Mn;

    // cp.async q,k planes (natural layout, padded stride)
#pragma unroll
    for (int it = 0; it < 8; it++) {
        const int sid = tid + it * 256;       // 0..2047
        const int u = sid >> 4, seg = sid & 15;
        const uint32_t dof = (u * CP + seg * 8) * 2;
        const size_t sof = base + (size_t)u * Mn + seg * 8;
        CPASYNC16(uQh + dof,                      g_qh + sof);
        CPASYNC16(uQh + CPL * 2 + dof,            g_ql + sof);
        CPASYNC16(uQh + 2 * CPL * 2 + dof,        g_kh + sof);
        CPASYNC16(uQh + 3 * CPL * 2 + dof,        g_kl + sof);
    }
    CPCOMMIT();

    if (tid < 128) dpow[tid] = powf(DECAYF, (float)tid);

    // build V^T planes from gmem (scatter transpose)
#pragma unroll
    for (int it = 0; it < 8; it++) {
        const int task = tid + it * 256;      // 0..2047
        const int u = task & 127, i0 = (task >> 7) * 8;
        uint4 dh = *(const uint4*)(g_vh + base + (size_t)u * Mn + i0);
        uint4 dl = *(const uint4*)(g_vl + base + (size_t)u * Mn + i0);
        const bf* ph = (const bf*)&dh;
        const bf* pl = (const bf*)&dl;
#pragma unroll
        for (int j = 0; j < 8; j++) {
            Vth[(i0 + j) * CP + u] = ph[j];
            Vtl[(i0 + j) * CP + u] = pl[j];
        }
    }

    asm volatile("cp.async.wait_group 0;");
    __syncthreads();

    // GEMM1: S[t][u] = q_t . k_u
    float acc[2][8][4];
#pragma unroll
    for (int mt = 0; mt < 2; mt++)
#pragma unroll
        for (int nt = 0; nt < 8; nt++)
#pragma unroll
            for (int r = 0; r < 4; r++) acc[mt][nt][r] = 0.f;
    gemm_sm_bf16(Qh, Ql, Kh, Kl, acc, wm, wn, g, t4);

    // mask + decay*lr
#pragma unroll
    for (int mt = 0; mt < 2; mt++)
#pragma unroll
        for (int nt = 0; nt < 8; nt++)
#pragma unroll
            for (int r = 0; r < 4; r++) {
                const int t = wm * 32 + mt * 16 + g + ((r >= 2) ? 8 : 0);
                const int u = wn * 64 + nt * 8 + 2 * t4 + (r & 1);
                acc[mt][nt][r] = (u < t) ? acc[mt][nt][r] * (LRF * dpow[t - 1 - u]) : 0.f;
            }
    __syncthreads();   // all warps done reading Q planes

    // store S planes over Q area
#pragma unroll
    for (int mt = 0; mt < 2; mt++) {
        const int r0 = wm * 32 + mt * 16 + g;
#pragma unroll
        for (int nt = 0; nt < 8; nt++) {
            const int c0 = wn * 64 + nt * 8 + 2 * t4;
            bf h0,l0,h1,l1;
            splitf(acc[mt][nt][0], h0, l0); splitf(acc[mt][nt][1], h1, l1);
            *(uint32_t*)(Qh + r0 * CP + c0) = pack2(h0, h1);
            *(uint32_t*)(Ql + r0 * CP + c0) = pack2(l0, l1);
            splitf(acc[mt][nt][2], h0, l0); splitf(acc[mt][nt][3], h1, l1);
            *(uint32_t*)(Qh + (r0 + 8) * CP + c0) = pack2(h0, h1);
            *(uint32_t*)(Ql + (r0 + 8) * CP + c0) = pack2(l0, l1);
        }
    }
    __syncthreads();

    // GEMM2: out[t][i] = S x V^T  -> g_att (fp32)
    float acc2[2][8][4];
#pragma unroll
    for (int mt = 0; mt < 2; mt++)
#pragma unroll
        for (int nt = 0; nt < 8; nt++)
#pragma unroll
            for (int r = 0; r < 4; r++) acc2[mt][nt][r] = 0.f;
    gemm_sm_bf16(Qh, Ql, Vth, Vtl, acc2, wm, wn, g, t4);
#pragma unroll
    for (int mt = 0; mt < 2; mt++) {
        const int r0 = wm * 32 + mt * 16 + g;
#pragma unroll
        for (int nt = 0; nt < 8; nt++) {
            const int c0 = wn * 64 + nt * 8 + 2 * t4;
            *(float2*)(g_att + base + (size_t)r0 * Mn + c0)       = make_float2(acc2[mt][nt][0], acc2[mt][nt][1]);
            *(float2*)(g_att + base + (size_t)(r0 + 8) * Mn + c0) = make_float2(acc2[mt][nt][2], acc2[mt][nt][3]);
        }
    }
    __syncthreads();   // done reading S planes

    // build Ktw planes over Q/S area: Ktw[j][u] = (k[u][j]) * lr*decay^(127-u)
#pragma unroll
    for (int it = 0; it < 8; it++) {
        const int task = tid + it * 256;
        const int u = task & 127, j0 = (task >> 7) * 8;
        const float w = LRF * dpow[127 - u];
#pragma unroll
        for (int j = 0; j < 8; j++) {
            float f = (__bfloat162float(Kh[u * CP + j0 + j]) +
                       __bfloat162float(Kl[u * CP + j0 + j])) * w;
            bf h, l; splitf(f, h, l);
            Qh[(j0 + j) * CP + u] = h;
            Ql[(j0 + j) * CP + u] = l;
        }
    }
    __syncthreads();

    // GEMM3: dS[i][j] = V^T x Ktw -> g_dS (fp32)
    float acc3[2][8][4];
#pragma unroll
    for (int mt = 0; mt < 2; mt++)
#pragma unroll
        for (int nt = 0; nt < 8; nt++)
#pragma unroll
            for (int r = 0; r < 4; r++) acc3[mt][nt][r] = 0.f;
    gemm_sm_bf16(Vth, Vtl, Qh, Ql, acc3, wm, wn, g, t4);

    const size_t dsbase = ((size_t)b * NCn + c) * (Mn * Mn);
#pragma unroll
    for (int mt = 0; mt < 2; mt++) {
        const int r0 = wm * 32 + mt * 16 + g;
#pragma unroll
        for (int nt = 0; nt < 8; nt++) {
            const int c0 = wn * 64 + nt * 8 + 2 * t4;
            *(float2*)(g_dS + dsbase + (size_t)r0 * Mn + c0)       = make_float2(acc3[mt][nt][0], acc3[mt][nt][1]);
            *(float2*)(g_dS + dsbase + (size_t)(r0 + 8) * Mn + c0) = make_float2(acc3[mt][nt][2], acc3[mt][nt][3]);
        }
    }
}

// ===========================================================================
// K3: prefix over chunks; emits S planes + final state (fp32)
// ===========================================================================
__global__ void __launch_bounds__(256) scan_kernel(float* __restrict__ state_out)
{
    const int gidx = blockIdx.x * blockDim.x + threadIdx.x;
    const int b  = gidx >> 14;
    const int ij = gidx & 16383;
    const float dc = powf(DECAYF, (float)Cn);
    float s = 0.f;
    for (int c = 0; c < NCn; c++) {
        const size_t idx = ((size_t)b * NCn + c) * 16384 + ij;
        bf h, l; splitf(s, h, l);
        g_Sh[idx] = h; g_Sl[idx] = l;
        s = dc * s + g_dS[idx];
    }
    state_out[gidx] = s;
}

// ===========================================================================
extern "C" void kernel_launch(void* const* d_in, const int* in_sizes, int n_in,
                              void* d_out, int out_size)
{
    const float* x  = (const float*)d_in[0];
    const float* Wk = (const float*)d_in[1];
    const float* bk = (const float*)d_in[2];
    const float* Wv = (const float*)d_in[3];
    const float* bv = (const float*)d_in[4];
    const float* Wq = (const float*)d_in[5];
    const float* bq = (const float*)d_in[6];
    const float* Wo = (const float*)d_in[7];
    const float* bo = (const float*)d_in[8];

    float* y         = (float*)d_out;
    float* state_out = y + (size_t)BSn * Dn;

    const int MIX_SMEM   = 12 * STG * 2;           // 73728
    const int INTER_SMEM = 16 * STG * 2;           // 98304
    const int CHUNK_SMEM = 6 * CPL * 2 + 512;      // 209408

    cudaFuncSetAttribute(proj_kernel,    cudaFuncAttributeMaxDynamicSharedMemorySize, MIX_SMEM);
    cudaFuncSetAttribute(outproj_kernel, cudaFuncAttributeMaxDynamicSharedMemorySize, MIX_SMEM);
    cudaFuncSetAttribute(inter_kernel,   cudaFuncAttributeMaxDynamicSharedMemorySize, INTER_SMEM);
    cudaFuncSetAttribute(chunk_kernel,   cudaFuncAttributeMaxDynamicSharedMemorySize, CHUNK_SMEM);

    conv_w_kernel<<<2048, 256>>>(Wk, Wv, Wq, Wo);
    proj_kernel<<<dim3(BSn / 128, 3), 256, MIX_SMEM>>>(x, bk, bv, bq);
    chunk_kernel<<<Bn * NCn, 256, CHUNK_SMEM>>>();
    scan_kernel<<<(Bn * Mn * Mn) / 256, 256>>>(state_out);
    inter_kernel<<<Bn * NCn, 256, INTER_SMEM>>>();
    outproj_kernel<<<dim3(BSn / 128, Dn / 128), 256, MIX_SMEM>>>(bo, y);
}

// round 7
// speedup vs baseline: 1.2062x; 1.2062x over previous
#include <cuda_runtime.h>
#include <math.h>
#include <stdint.h>

// Problem constants
#define Bn   4
#define Sn   4096
#define Dn   1024
#define Mn   128
#define Cn   128
#define NCn  (Sn / Cn)
#define BSn  (Bn * Sn)
#define DECAYF 0.99f
#define LRF    0.01f

// Scratch (device globals)
__device__ float g_k  [BSn * Mn];
__device__ float g_v  [BSn * Mn];
__device__ float g_q  [BSn * Mn];
__device__ float g_att[BSn * Mn];
__device__ float g_dS [Bn * NCn * Mn * Mn];
__device__ float g_S  [Bn * NCn * Mn * Mn];       // tf32-pre-rounded (B operand only)
__device__ float g_W  [4 * 128 * 1024];           // Wk|Wv|Wq|Wo, tf32-pre-rounded

// ===========================================================================
// helpers
// ===========================================================================
__device__ __forceinline__ uint32_t smem_u32(const void* p) {
    uint32_t a;
    asm("{ .reg .u64 t; cvta.to.shared.u64 t, %1; cvt.u32.u64 %0, t; }"
        : "=r"(a) : "l"(p));
    return a;
}
__device__ __forceinline__ float to_tf32(float x) {
    float y;
    asm("cvt.rna.tf32.f32 %0, %1;" : "=f"(y) : "f"(x));
    return y;
}
__device__ __forceinline__ void mma_16n8k8(float* d, const uint32_t* a, const uint32_t* b) {
    asm volatile(
        "mma.sync.aligned.m16n8k8.row.col.f32.tf32.tf32.f32 "
        "{%0,%1,%2,%3}, {%4,%5,%6,%7}, {%8,%9}, {%0,%1,%2,%3};"
        : "+f"(d[0]), "+f"(d[1]), "+f"(d[2]), "+f"(d[3])
        : "r"(a[0]), "r"(a[1]), "r"(a[2]), "r"(a[3]), "r"(b[0]), "r"(b[1]));
}
#define CPASYNC16(sa, gp) \
    asm volatile("cp.async.ca.shared.global [%0], [%1], 16;" :: "r"(sa), "l"(gp))
#define CPCOMMIT() asm volatile("cp.async.commit_group;")
#define CPWAIT2()  asm volatile("cp.async.wait_group 2;")

extern __shared__ float sm_dyn[];

// ===========================================================================
// conv_w: pre-round weights to tf32 (stored as fp32) — removes B-side cvt.
// ===========================================================================
__global__ void __launch_bounds__(256) conv_w_kernel(
    const float* __restrict__ Wk, const float* __restrict__ Wv,
    const float* __restrict__ Wq, const float* __restrict__ Wo)
{
    const int i = blockIdx.x * 256 + threadIdx.x;   // < 524288
    float v;
    if (i < 131072)       v = Wk[i];
    else if (i < 262144)  v = Wv[i - 131072];
    else if (i < 393216)  v = Wq[i - 262144];
    else                  v = Wo[i - 393216];
    g_W[i] = to_tf32(v);
}

// ===========================================================================
// Shared tf32 GEMM, cp.async 4-stage pipeline.
// C[128,128] = A[128,K] * Bm^T (+bias / +=rowscale). 256 thr, 8 warps 4x2,
// warp tile 32x64, K-chunk 16. B operand is pre-rounded tf32 (no cvt).
// Dynamic smem: 4*2560*2 floats = 81920 B.
// ===========================================================================
#define SMLD 20
#define STGF 2560

template<bool ACCUM, bool ROWSCALE>
__device__ __forceinline__ void gemm_v2(
    const float* __restrict__ A, int lda,
    const float* __restrict__ Bm, int ldb, int K,
    const float* __restrict__ bias,
    float* __restrict__ C, int ldc)
{
    float* sA = sm_dyn;
    float* sB = sm_dyn + 4 * STGF;
    const uint32_t sAu = smem_u32(sA);
    const uint32_t sBu = smem_u32(sB);
    const int tid = threadIdx.x;
    const int lane = tid & 31, wid = tid >> 5;
    const int wm = wid >> 1, wn = wid & 1;
    const int g = lane >> 2, t4 = lane & 3;

    const int row0 = tid >> 2,          c40 = (tid & 3) * 4;
    const int row1 = (tid + 256) >> 2,  c41 = c40;

    float acc[2][8][4];
#pragma unroll
    for (int mt = 0; mt < 2; mt++)
#pragma unroll
        for (int nt = 0; nt < 8; nt++)
#pragma unroll
            for (int r = 0; r < 4; r++) acc[mt][nt][r] = 0.f;

    const int nc = K >> 4;

#define ISSUE(ch) do { \
    const int _buf = (ch) & 3; \
    const int _k0 = (ch) * 16; \
    CPASYNC16(sAu + (_buf * STGF + row0 * SMLD + c40) * 4, A  + (size_t)row0 * lda + _k0 + c40); \
    CPASYNC16(sBu + (_buf * STGF + row0 * SMLD + c40) * 4, Bm + (size_t)row0 * ldb + _k0 + c40); \
    CPASYNC16(sAu + (_buf * STGF + row1 * SMLD + c41) * 4, A  + (size_t)row1 * lda + _k0 + c41); \
    CPASYNC16(sBu + (_buf * STGF + row1 * SMLD + c41) * 4, Bm + (size_t)row1 * ldb + _k0 + c41); \
} while (0)

    ISSUE(0); CPCOMMIT();
    ISSUE(1); CPCOMMIT();
    ISSUE(2); CPCOMMIT();

    for (int ch = 0; ch < nc; ch++) {
        CPWAIT2();
        __syncthreads();
        if (ch + 3 < nc) ISSUE(ch + 3);
        CPCOMMIT();

        const float* pa = sA + (ch & 3) * STGF;
        const float* pb = sB + (ch & 3) * STGF;
#pragma unroll
        for (int ks = 0; ks < 2; ks++) {
            const int ko = ks * 8;
            uint32_t af[2][4];
#pragma unroll
            for (int mt = 0; mt < 2; mt++) {
                const int br = wm * 32 + mt * 16;
                af[mt][0] = __float_as_uint(to_tf32(pa[(br + g    ) * SMLD + ko + t4    ]));
                af[mt][1] = __float_as_uint(to_tf32(pa[(br + g + 8) * SMLD + ko + t4    ]));
                af[mt][2] = __float_as_uint(to_tf32(pa[(br + g    ) * SMLD + ko + t4 + 4]));
                af[mt][3] = __float_as_uint(to_tf32(pa[(br + g + 8) * SMLD + ko + t4 + 4]));
            }
#pragma unroll
            for (int nt = 0; nt < 8; nt++) {
                const int bn = wn * 64 + nt * 8 + g;
                uint32_t bf[2];
                bf[0] = __float_as_uint(pb[bn * SMLD + ko + t4    ]);   // pre-rounded
                bf[1] = __float_as_uint(pb[bn * SMLD + ko + t4 + 4]);
                mma_16n8k8(acc[0][nt], af[0], bf);
                mma_16n8k8(acc[1][nt], af[1], bf);
            }
        }
    }
#undef ISSUE

#pragma unroll
    for (int mt = 0; mt < 2; mt++) {
        const int r0 = wm * 32 + mt * 16 + g;
#pragma unroll
        for (int nt = 0; nt < 8; nt++) {
            const int c0 = wn * 64 + nt * 8 + 2 * t4;
            float* p0 = C + (size_t)r0 * ldc + c0;
            float* p1 = C + (size_t)(r0 + 8) * ldc + c0;
            if (ACCUM) {
                float s0 = 1.f, s1 = 1.f;
                if (ROWSCALE) { s0 = powf(DECAYF, (float)r0); s1 = powf(DECAYF, (float)(r0 + 8)); }
                float2 o0 = *(float2*)p0, o1 = *(float2*)p1;
                o0.x += s0 * acc[mt][nt][0]; o0.y += s0 * acc[mt][nt][1];
                o1.x += s1 * acc[mt][nt][2]; o1.y += s1 * acc[mt][nt][3];
                *(float2*)p0 = o0; *(float2*)p1 = o1;
            } else {
                float b0 = bias ? bias[c0] : 0.f;
                float b1 = bias ? bias[c0 + 1] : 0.f;
                float2 o0, o1;
                o0.x = acc[mt][nt][0] + b0; o0.y = acc[mt][nt][1] + b1;
                o1.x = acc[mt][nt][2] + b0; o1.y = acc[mt][nt][3] + b1;
                *(float2*)p0 = o0; *(float2*)p1 = o1;
            }
        }
    }
}

// ===========================================================================
// K1: projections   grid (128, 3)
// ===========================================================================
__global__ void __launch_bounds__(256, 2) proj_mma_kernel(
    const float* __restrict__ x,
    const float* __restrict__ bk, const float* __restrict__ bv,
    const float* __restrict__ bq)
{
    const size_t rb = (size_t)blockIdx.x * 128;
    const int yv = blockIdx.y;
    const float* bias = (yv == 0) ? bk : (yv == 1) ? bv : bq;
    float* outp = (yv == 0) ? g_k : (yv == 1) ? g_v : g_q;
    gemm_v2<false, false>(x + rb * Dn, Dn, g_W + (size_t)yv * 131072, Dn, Dn,
                          bias, outp + rb * Mn, Mn);
}

// ===========================================================================
// K5: y = att @ Wo^T + bo   grid (128, 8)
// ===========================================================================
__global__ void __launch_bounds__(256, 2) outproj_mma_kernel(
    const float* __restrict__ bo, float* __restrict__ y)
{
    const size_t rb = (size_t)blockIdx.x * 128;
    const int    cb = blockIdx.y * 128;
    gemm_v2<false, false>(g_att + rb * Mn, Mn, g_W + 393216 + (size_t)cb * Mn, Mn, Mn,
                          bo + cb, y + rb * Dn + cb, Dn);
}

// ===========================================================================
// K4: out[t][i] += decay^t * sum_j S_c[i][j]*q_t[j]   grid (128)
// ===========================================================================
__global__ void __launch_bounds__(256, 2) inter_mma_kernel()
{
    const int b = blockIdx.x / NCn;
    const int c = blockIdx.x % NCn;
    const size_t base  = ((size_t)b * Sn + (size_t)c * Cn) * Mn;
    const size_t sbase = ((size_t)b * NCn + c) * 16384;
    gemm_v2<true, true>(g_q + base, Mn, g_S + sbase, Mn, Mn,
                        (const float*)nullptr, g_att + base, Mn);
}

// ===========================================================================
// K2 (tensor, 3xTF32 compensated): per (b,c) — as R4
// ===========================================================================
#define SP 132

__device__ __forceinline__ void split4(const float* v, uint32_t* hi, uint32_t* lo) {
#pragma unroll
    for (int i = 0; i < 4; i++) {
        float h = to_tf32(v[i]);
        hi[i] = __float_as_uint(h);
        lo[i] = __float_as_uint(to_tf32(v[i] - h));
    }
}
__device__ __forceinline__ void split2(const float* v, uint32_t* hi, uint32_t* lo) {
#pragma unroll
    for (int i = 0; i < 2; i++) {
        float h = to_tf32(v[i]);
        hi[i] = __float_as_uint(h);
        lo[i] = __float_as_uint(to_tf32(v[i] - h));
    }
}

__device__ __forceinline__ void gemm3x_128(const float* __restrict__ Am,
                                           const float* __restrict__ Bmm,
                                           float acc[2][8][4],
                                           int wm, int wn, int g, int t4)
{
#pragma unroll 4
    for (int ks = 0; ks < 16; ks++) {
        const int ko = ks * 8;
        uint32_t ah[2][4], al[2][4];
#pragma unroll
        for (int mt = 0; mt < 2; mt++) {
            const int br = wm * 32 + mt * 16;
            float av[4];
            av[0] = Am[(br + g    ) * SP + ko + t4    ];
            av[1] = Am[(br + g + 8) * SP + ko + t4    ];
            av[2] = Am[(br + g    ) * SP + ko + t4 + 4];
            av[3] = Am[(br + g + 8) * SP + ko + t4 + 4];
            split4(av, ah[mt], al[mt]);
        }
#pragma unroll
        for (int nt = 0; nt < 8; nt++) {
            const int bn = wn * 64 + nt * 8 + g;
            float bv[2];
            bv[0] = Bmm[bn * SP + ko + t4    ];
            bv[1] = Bmm[bn * SP + ko + t4 + 4];
            uint32_t bh[2], bl[2];
            split2(bv, bh, bl);
#pragma unroll
            for (int mt = 0; mt < 2; mt++) {
                mma_16n8k8(acc[mt][nt], ah[mt], bh);
                mma_16n8k8(acc[mt][nt], al[mt], bh);
                mma_16n8k8(acc[mt][nt], ah[mt], bl);
            }
        }
    }
}

__global__ void __launch_bounds__(256) chunk_mma_kernel()
{
    float* B0   = sm_dyn;              // K natural -> V^T
    float* B1   = B0 + 128 * SP;       // Q natural -> S -> Ktw
    float* dpow = B1 + 128 * SP;

    const int tid = threadIdx.x;
    const int lane = tid & 31, wid = tid >> 5;
    const int wm = wid >> 1, wn = wid & 1;
    const int g = lane >> 2, t4 = lane & 3;
    const int b = blockIdx.x / NCn;
    const int c = blockIdx.x % NCn;
    const size_t base = ((size_t)b * Sn + (size_t)c * Cn) * Mn;

#pragma unroll
    for (int it = 0; it < 16; it++) {
        const int idx = (tid + it * 256) * 4;
        const int r = idx >> 7, d = idx & 127;
        *(float4*)(B0 + r * SP + d) = *(const float4*)(g_k + base + idx);
        *(float4*)(B1 + r * SP + d) = *(const float4*)(g_q + base + idx);
    }
    if (tid < 128) dpow[tid] = powf(DECAYF, (float)tid);
    __syncthreads();

    float acc[2][8][4];
#pragma unroll
    for (int mt = 0; mt < 2; mt++)
#pragma unroll
        for (int nt = 0; nt < 8; nt++)
#pragma unroll
            for (int r = 0; r < 4; r++) acc[mt][nt][r] = 0.f;
    gemm3x_128(B1, B0, acc, wm, wn, g, t4);

#pragma unroll
    for (int mt = 0; mt < 2; mt++)
#pragma unroll
        for (int nt = 0; nt < 8; nt++)
#pragma unroll
            for (int r = 0; r < 4; r++) {
                const int t = wm * 32 + mt * 16 + g + ((r >= 2) ? 8 : 0);
                const int u = wn * 64 + nt * 8 + 2 * t4 + (r & 1);
                acc[mt][nt][r] = (u < t) ? acc[mt][nt][r] * (LRF * dpow[t - 1 - u]) : 0.f;
            }
    __syncthreads();

#pragma unroll
    for (int mt = 0; mt < 2; mt++) {
        const int r0 = wm * 32 + mt * 16 + g;
#pragma unroll
        for (int nt = 0; nt < 8; nt++) {
            const int c0 = wn * 64 + nt * 8 + 2 * t4;
            *(float2*)(B1 + r0 * SP + c0)       = make_float2(acc[mt][nt][0], acc[mt][nt][1]);
            *(float2*)(B1 + (r0 + 8) * SP + c0) = make_float2(acc[mt][nt][2], acc[mt][nt][3]);
        }
    }
#pragma unroll
    for (int it = 0; it < 16; it++) {
        const int idx = (tid + it * 256) * 4;
        const int u = idx >> 7, i0 = idx & 127;
        float4 v = *(const float4*)(g_v + base + idx);
        B0[(i0 + 0) * SP + u] = v.x;
        B0[(i0 + 1) * SP + u] = v.y;
        B0[(i0 + 2) * SP + u] = v.z;
        B0[(i0 + 3) * SP + u] = v.w;
    }
    __syncthreads();

    float acc2[2][8][4];
#pragma unroll
    for (int mt = 0; mt < 2; mt++)
#pragma unroll
        for (int nt = 0; nt < 8; nt++)
#pragma unroll
            for (int r = 0; r < 4; r++) acc2[mt][nt][r] = 0.f;
    gemm3x_128(B1, B0, acc2, wm, wn, g, t4);
#pragma unroll
    for (int mt = 0; mt < 2; mt++) {
        const int r0 = wm * 32 + mt * 16 + g;
#pragma unroll
        for (int nt = 0; nt < 8; nt++) {
            const int c0 = wn * 64 + nt * 8 + 2 * t4;
            *(float2*)(g_att + base + (size_t)r0 * Mn + c0)       = make_float2(acc2[mt][nt][0], acc2[mt][nt][1]);
            *(float2*)(g_att + base + (size_t)(r0 + 8) * Mn + c0) = make_float2(acc2[mt][nt][2], acc2[mt][nt][3]);
        }
    }
    __syncthreads();

#pragma unroll
    for (int it = 0; it < 16; it++) {
        const int idx = (tid + it * 256) * 4;
        const int u = idx >> 7, j0 = idx & 127;
        const float w = LRF * dpow[127 - u];
        float4 k = *(const float4*)(g_k + base + idx);
        B1[(j0 + 0) * SP + u] = k.x * w;
        B1[(j0 + 1) * SP + u] = k.y * w;
        B1[(j0 + 2) * SP + u] = k.z * w;
        B1[(j0 + 3) * SP + u] = k.w * w;
    }
    __syncthreads();

    float acc3[2][8][4];
#pragma unroll
    for (int mt = 0; mt < 2; mt++)
#pragma unroll
        for (int nt = 0; nt < 8; nt++)
#pragma unroll
            for (int r = 0; r < 4; r++) acc3[mt][nt][r] = 0.f;
    gemm3x_128(B0, B1, acc3, wm, wn, g, t4);

    const size_t dsbase = ((size_t)b * NCn + c) * (Mn * Mn);
#pragma unroll
    for (int mt = 0; mt < 2; mt++) {
        const int r0 = wm * 32 + mt * 16 + g;
#pragma unroll
        for (int nt = 0; nt < 8; nt++) {
            const int c0 = wn * 64 + nt * 8 + 2 * t4;
            *(float2*)(g_dS + dsbase + (size_t)r0 * Mn + c0)       = make_float2(acc3[mt][nt][0], acc3[mt][nt][1]);
            *(float2*)(g_dS + dsbase + (size_t)(r0 + 8) * Mn + c0) = make_float2(acc3[mt][nt][2], acc3[mt][nt][3]);
        }
    }
}

// ===========================================================================
// K3: prefix over chunks; store S tf32-pre-rounded (exactly the cvt inter did)
// ===========================================================================
__global__ void __launch_bounds__(256) scan_kernel(float* __restrict__ state_out)
{
    const int gg = blockIdx.x * blockDim.x + threadIdx.x;
    const int b  = gg >> 14;
    const int ij = gg & 16383;
    const float dc = powf(DECAYF, (float)Cn);
    float s = 0.f;
    for (int c = 0; c < NCn; c++) {
        const size_t idx = ((size_t)b * NCn + c) * 16384 + ij;
        g_S[idx] = to_tf32(s);
        s = dc * s + g_dS[idx];
    }
    state_out[gg] = s;
}

// ===========================================================================
extern "C" void kernel_launch(void* const* d_in, const int* in_sizes, int n_in,
                              void* d_out, int out_size)
{
    const float* x  = (const float*)d_in[0];
    const float* Wk = (const float*)d_in[1];
    const float* bk = (const float*)d_in[2];
    const float* Wv = (const float*)d_in[3];
    const float* bv = (const float*)d_in[4];
    const float* Wq = (const float*)d_in[5];
    const float* bq = (const float*)d_in[6];
    const float* Wo = (const float*)d_in[7];
    const float* bo = (const float*)d_in[8];

    float* y         = (float*)d_out;
    float* state_out = y + (size_t)BSn * Dn;

    const int GEMM_SMEM  = 4 * STGF * 2 * 4;                 // 81920
    const int CHUNK_SMEM = (2 * 128 * SP + 128) * 4 + 512;

    cudaFuncSetAttribute(proj_mma_kernel,    cudaFuncAttributeMaxDynamicSharedMemorySize, GEMM_SMEM);
    cudaFuncSetAttribute(outproj_mma_kernel, cudaFuncAttributeMaxDynamicSharedMemorySize, GEMM_SMEM);
    cudaFuncSetAttribute(inter_mma_kernel,   cudaFuncAttributeMaxDynamicSharedMemorySize, GEMM_SMEM);
    cudaFuncSetAttribute(chunk_mma_kernel,   cudaFuncAttributeMaxDynamicSharedMemorySize, CHUNK_SMEM);

    conv_w_kernel<<<2048, 256>>>(Wk, Wv, Wq, Wo);
    proj_mma_kernel<<<dim3(BSn / 128, 3), 256, GEMM_SMEM>>>(x, bk, bv, bq);
    chunk_mma_kernel<<<Bn * NCn, 256, CHUNK_SMEM>>>();
    scan_kernel<<<(Bn * Mn * Mn) / 256, 256>>>(state_out);
    inter_mma_kernel<<<Bn * NCn, 256, GEMM_SMEM>>>();
    outproj_mma_kernel<<<dim3(BSn / 128, Dn / 128), 256, GEMM_SMEM>>>(bo, y);
}

// round 8
// speedup vs baseline: 1.4021x; 1.1624x over previous
#include <cuda_runtime.h>
#include <cuda_fp16.h>
#include <math.h>
#include <stdint.h>

// Problem constants
#define Bn   4
#define Sn   4096
#define Dn   1024
#define Mn   128
#define Cn   128
#define NCn  (Sn / Cn)
#define BSn  (Bn * Sn)
#define DECAYF 0.99f
#define LRF    0.01f

// Scratch (device globals)
__device__ float  g_k  [BSn * Mn];
__device__ float  g_v  [BSn * Mn];
__device__ float  g_q  [BSn * Mn];
__device__ float  g_att[BSn * Mn];
__device__ float  g_dS [Bn * NCn * Mn * Mn];
__device__ __half g_S16[Bn * NCn * Mn * Mn];      // S pre-converted (B operand of inter)
__device__ __half g_W16[4 * 128 * 1024];          // Wk|Wv|Wq|Wo as f16

// ===========================================================================
// helpers
// ===========================================================================
__device__ __forceinline__ uint32_t smem_u32(const void* p) {
    uint32_t a;
    asm("{ .reg .u64 t; cvta.to.shared.u64 t, %1; cvt.u32.u64 %0, t; }"
        : "=r"(a) : "l"(p));
    return a;
}
__device__ __forceinline__ float to_tf32(float x) {
    float y;
    asm("cvt.rna.tf32.f32 %0, %1;" : "=f"(y) : "f"(x));
    return y;
}
__device__ __forceinline__ void mma_f16(float* d, const uint32_t* a, const uint32_t* b) {
    asm volatile(
        "mma.sync.aligned.m16n8k16.row.col.f32.f16.f16.f32 "
        "{%0,%1,%2,%3}, {%4,%5,%6,%7}, {%8,%9}, {%0,%1,%2,%3};"
        : "+f"(d[0]), "+f"(d[1]), "+f"(d[2]), "+f"(d[3])
        : "r"(a[0]), "r"(a[1]), "r"(a[2]), "r"(a[3]), "r"(b[0]), "r"(b[1]));
}
__device__ __forceinline__ void mma_16n8k8(float* d, const uint32_t* a, const uint32_t* b) {
    asm volatile(
        "mma.sync.aligned.m16n8k8.row.col.f32.tf32.tf32.f32 "
        "{%0,%1,%2,%3}, {%4,%5,%6,%7}, {%8,%9}, {%0,%1,%2,%3};"
        : "+f"(d[0]), "+f"(d[1]), "+f"(d[2]), "+f"(d[3])
        : "r"(a[0]), "r"(a[1]), "r"(a[2]), "r"(a[3]), "r"(b[0]), "r"(b[1]));
}
#define CPASYNC16(sa, gp) \
    asm volatile("cp.async.ca.shared.global [%0], [%1], 16;" :: "r"(sa), "l"(gp))
#define CPCOMMIT() asm volatile("cp.async.commit_group;")
#define CPWAIT2()  asm volatile("cp.async.wait_group 2;")

extern __shared__ float sm_dyn[];

// ===========================================================================
// conv_w: weights -> f16
// ===========================================================================
__global__ void __launch_bounds__(256) conv_w_kernel(
    const float* __restrict__ Wk, const float* __restrict__ Wv,
    const float* __restrict__ Wq, const float* __restrict__ Wo)
{
    const int i = blockIdx.x * 256 + threadIdx.x;   // < 524288
    float v;
    if (i < 131072)       v = Wk[i];
    else if (i < 262144)  v = Wv[i - 131072];
    else if (i < 393216)  v = Wq[i - 262144];
    else                  v = Wo[i - 393216];
    g_W16[i] = __float2half_rn(v);
}

// ===========================================================================
// f16 GEMM: A fp32 (register double-buffer, cvt at staging), B f16 (cp.async
// 4-stage). C[128,128] = A[128,K] * B^T (+bias / +=rowscale).
// 256 thr, 8 warps 4x2, warp tile 32x64, K-chunk 16.
// smem: sA[2][3072] + sB[4][3072] halves = 36864 B.
// ===========================================================================
#define SROWH 24      // halves per row (48 B) — conflict-free frag loads
#define STGH  3072    // halves per stage

template<bool ACCUM, bool ROWSCALE>
__device__ __forceinline__ void gemm_f16(
    const float* __restrict__ A, int lda,
    const __half* __restrict__ Bm, int ldb, int K,
    const float* __restrict__ bias,
    float* __restrict__ C, int ldc)
{
    __half* sA = (__half*)sm_dyn;
    __half* sB = sA + 2 * STGH;
    const uint32_t sBu = smem_u32(sB);
    const int tid = threadIdx.x;
    const int lane = tid & 31, wid = tid >> 5;
    const int wm = wid >> 1, wn = wid & 1;
    const int g = lane >> 2, t4 = lane & 3;
    const int row = tid >> 1, half = tid & 1;

    float acc[2][8][4];
#pragma unroll
    for (int mt = 0; mt < 2; mt++)
#pragma unroll
        for (int nt = 0; nt < 8; nt++)
#pragma unroll
            for (int r = 0; r < 4; r++) acc[mt][nt][r] = 0.f;

    const int nc = K >> 4;

#define ISSUE_B(ch) do { \
    const uint32_t _d = (((ch) & 3) * STGH + row * SROWH + half * 8) * 2; \
    CPASYNC16(sBu + _d, Bm + (size_t)row * ldb + (ch) * 16 + half * 8); \
} while (0)

    ISSUE_B(0); CPCOMMIT();
    ISSUE_B(1); CPCOMMIT();
    ISSUE_B(2); CPCOMMIT();

    float pre[8];
    {
        const float* ap = A + (size_t)row * lda + half * 8;
        float4 a0 = *(const float4*)ap, a1 = *(const float4*)(ap + 4);
        pre[0]=a0.x; pre[1]=a0.y; pre[2]=a0.z; pre[3]=a0.w;
        pre[4]=a1.x; pre[5]=a1.y; pre[6]=a1.z; pre[7]=a1.w;
    }

    for (int ch = 0; ch < nc; ch++) {
        // convert + store A chunk
        {
            uint32_t w[4];
#pragma unroll
            for (int j = 0; j < 4; j++) {
                __half2 h = __floats2half2_rn(pre[2*j], pre[2*j+1]);
                w[j] = *(uint32_t*)&h;
            }
            *(uint4*)(sA + (ch & 1) * STGH + row * SROWH + half * 8) = *(uint4*)w;
        }
        if (ch + 1 < nc) {
            const float* ap = A + (size_t)row * lda + (ch + 1) * 16 + half * 8;
            float4 a0 = *(const float4*)ap, a1 = *(const float4*)(ap + 4);
            pre[0]=a0.x; pre[1]=a0.y; pre[2]=a0.z; pre[3]=a0.w;
            pre[4]=a1.x; pre[5]=a1.y; pre[6]=a1.z; pre[7]=a1.w;
        }
        CPWAIT2();
        __syncthreads();
        if (ch + 3 < nc) ISSUE_B(ch + 3);
        CPCOMMIT();

        const __half* pA = sA + (ch & 1) * STGH;
        const __half* pB = sB + (ch & 3) * STGH;

        uint32_t af[2][4];
#pragma unroll
        for (int mt = 0; mt < 2; mt++) {
            const int br = wm * 32 + mt * 16;
            af[mt][0] = *(const uint32_t*)(pA + (br + g    ) * SROWH + 2 * t4);
            af[mt][1] = *(const uint32_t*)(pA + (br + g + 8) * SROWH + 2 * t4);
            af[mt][2] = *(const uint32_t*)(pA + (br + g    ) * SROWH + 2 * t4 + 8);
            af[mt][3] = *(const uint32_t*)(pA + (br + g + 8) * SROWH + 2 * t4 + 8);
        }
#pragma unroll
        for (int nt = 0; nt < 8; nt++) {
            const int bn = wn * 64 + nt * 8 + g;
            uint32_t bf[2];
            bf[0] = *(const uint32_t*)(pB + bn * SROWH + 2 * t4);
            bf[1] = *(const uint32_t*)(pB + bn * SROWH + 2 * t4 + 8);
            mma_f16(acc[0][nt], af[0], bf);
            mma_f16(acc[1][nt], af[1], bf);
        }
    }
#undef ISSUE_B

#pragma unroll
    for (int mt = 0; mt < 2; mt++) {
        const int r0 = wm * 32 + mt * 16 + g;
#pragma unroll
        for (int nt = 0; nt < 8; nt++) {
            const int c0 = wn * 64 + nt * 8 + 2 * t4;
            float* p0 = C + (size_t)r0 * ldc + c0;
            float* p1 = C + (size_t)(r0 + 8) * ldc + c0;
            if (ACCUM) {
                float s0 = 1.f, s1 = 1.f;
                if (ROWSCALE) { s0 = powf(DECAYF, (float)r0); s1 = powf(DECAYF, (float)(r0 + 8)); }
                float2 o0 = *(float2*)p0, o1 = *(float2*)p1;
                o0.x += s0 * acc[mt][nt][0]; o0.y += s0 * acc[mt][nt][1];
                o1.x += s1 * acc[mt][nt][2]; o1.y += s1 * acc[mt][nt][3];
                *(float2*)p0 = o0; *(float2*)p1 = o1;
            } else {
                float b0 = bias ? bias[c0] : 0.f;
                float b1 = bias ? bias[c0 + 1] : 0.f;
                float2 o0, o1;
                o0.x = acc[mt][nt][0] + b0; o0.y = acc[mt][nt][1] + b1;
                o1.x = acc[mt][nt][2] + b0; o1.y = acc[mt][nt][3] + b1;
                *(float2*)p0 = o0; *(float2*)p1 = o1;
            }
        }
    }
}

// ===========================================================================
// K1: projections   grid (128, 3)
// ===========================================================================
__global__ void __launch_bounds__(256, 2) proj_kernel(
    const float* __restrict__ x,
    const float* __restrict__ bk, const float* __restrict__ bv,
    const float* __restrict__ bq)
{
    const size_t rb = (size_t)blockIdx.x * 128;
    const int yv = blockIdx.y;
    const float* bias = (yv == 0) ? bk : (yv == 1) ? bv : bq;
    float* outp = (yv == 0) ? g_k : (yv == 1) ? g_v : g_q;
    gemm_f16<false, false>(x + rb * Dn, Dn, g_W16 + (size_t)yv * 131072, Dn, Dn,
                           bias, outp + rb * Mn, Mn);
}

// ===========================================================================
// K5: y = att @ Wo^T + bo   grid (128, 8)
// ===========================================================================
__global__ void __launch_bounds__(256, 2) outproj_kernel(
    const float* __restrict__ bo, float* __restrict__ y)
{
    const size_t rb = (size_t)blockIdx.x * 128;
    const int    cb = blockIdx.y * 128;
    gemm_f16<false, false>(g_att + rb * Mn, Mn, g_W16 + 393216 + (size_t)cb * Mn, Mn, Mn,
                           bo + cb, y + rb * Dn + cb, Dn);
}

// ===========================================================================
// K4: inter   grid (128)
// ===========================================================================
__global__ void __launch_bounds__(256, 2) inter_kernel()
{
    const int b = blockIdx.x / NCn;
    const int c = blockIdx.x % NCn;
    const size_t base  = ((size_t)b * Sn + (size_t)c * Cn) * Mn;
    const size_t sbase = ((size_t)b * NCn + c) * 16384;
    gemm_f16<true, true>(g_q + base, Mn, g_S16 + sbase, Mn, Mn,
                         (const float*)nullptr, g_att + base, Mn);
}

// ===========================================================================
// K2 (3xTF32 compensated, unchanged from R6): per (b,c)
// ===========================================================================
#define SP 132

__device__ __forceinline__ void split4(const float* v, uint32_t* hi, uint32_t* lo) {
#pragma unroll
    for (int i = 0; i < 4; i++) {
        float h = to_tf32(v[i]);
        hi[i] = __float_as_uint(h);
        lo[i] = __float_as_uint(to_tf32(v[i] - h));
    }
}
__device__ __forceinline__ void split2(const float* v, uint32_t* hi, uint32_t* lo) {
#pragma unroll
    for (int i = 0; i < 2; i++) {
        float h = to_tf32(v[i]);
        hi[i] = __float_as_uint(h);
        lo[i] = __float_as_uint(to_tf32(v[i] - h));
    }
}

__device__ __forceinline__ void gemm3x_128(const float* __restrict__ Am,
                                           const float* __restrict__ Bmm,
                                           float acc[2][8][4],
                                           int wm, int wn, int g, int t4)
{
#pragma unroll 4
    for (int ks = 0; ks < 16; ks++) {
        const int ko = ks * 8;
        uint32_t ah[2][4], al[2][4];
#pragma unroll
        for (int mt = 0; mt < 2; mt++) {
            const int br = wm * 32 + mt * 16;
            float av[4];
            av[0] = Am[(br + g    ) * SP + ko + t4    ];
            av[1] = Am[(br + g + 8) * SP + ko + t4    ];
            av[2] = Am[(br + g    ) * SP + ko + t4 + 4];
            av[3] = Am[(br + g + 8) * SP + ko + t4 + 4];
            split4(av, ah[mt], al[mt]);
        }
#pragma unroll
        for (int nt = 0; nt < 8; nt++) {
            const int bn = wn * 64 + nt * 8 + g;
            float bv[2];
            bv[0] = Bmm[bn * SP + ko + t4    ];
            bv[1] = Bmm[bn * SP + ko + t4 + 4];
            uint32_t bh[2], bl[2];
            split2(bv, bh, bl);
#pragma unroll
            for (int mt = 0; mt < 2; mt++) {
                mma_16n8k8(acc[mt][nt], ah[mt], bh);
                mma_16n8k8(acc[mt][nt], al[mt], bh);
                mma_16n8k8(acc[mt][nt], ah[mt], bl);
            }
        }
    }
}

__global__ void __launch_bounds__(256) chunk_kernel()
{
    float* B0   = sm_dyn;              // K natural -> V^T
    float* B1   = B0 + 128 * SP;       // Q natural -> S -> Ktw
    float* dpow = B1 + 128 * SP;

    const int tid = threadIdx.x;
    const int lane = tid & 31, wid = tid >> 5;
    const int wm = wid >> 1, wn = wid & 1;
    const int g = lane >> 2, t4 = lane & 3;
    const int b = blockIdx.x / NCn;
    const int c = blockIdx.x % NCn;
    const size_t base = ((size_t)b * Sn + (size_t)c * Cn) * Mn;

#pragma unroll
    for (int it = 0; it < 16; it++) {
        const int idx = (tid + it * 256) * 4;
        const int r = idx >> 7, d = idx & 127;
        *(float4*)(B0 + r * SP + d) = *(const float4*)(g_k + base + idx);
        *(float4*)(B1 + r * SP + d) = *(const float4*)(g_q + base + idx);
    }
    if (tid < 128) dpow[tid] = powf(DECAYF, (float)tid);
    __syncthreads();

    float acc[2][8][4];
#pragma unroll
    for (int mt = 0; mt < 2; mt++)
#pragma unroll
        for (int nt = 0; nt < 8; nt++)
#pragma unroll
            for (int r = 0; r < 4; r++) acc[mt][nt][r] = 0.f;
    gemm3x_128(B1, B0, acc, wm, wn, g, t4);

#pragma unroll
    for (int mt = 0; mt < 2; mt++)
#pragma unroll
        for (int nt = 0; nt < 8; nt++)
#pragma unroll
            for (int r = 0; r < 4; r++) {
                const int t = wm * 32 + mt * 16 + g + ((r >= 2) ? 8 : 0);
                const int u = wn * 64 + nt * 8 + 2 * t4 + (r & 1);
                acc[mt][nt][r] = (u < t) ? acc[mt][nt][r] * (LRF * dpow[t - 1 - u]) : 0.f;
            }
    __syncthreads();

#pragma unroll
    for (int mt = 0; mt < 2; mt++) {
        const int r0 = wm * 32 + mt * 16 + g;
#pragma unroll
        for (int nt = 0; nt < 8; nt++) {
            const int c0 = wn * 64 + nt * 8 + 2 * t4;
            *(float2*)(B1 + r0 * SP + c0)       = make_float2(acc[mt][nt][0], acc[mt][nt][1]);
            *(float2*)(B1 + (r0 + 8) * SP + c0) = make_float2(acc[mt][nt][2], acc[mt][nt][3]);
        }
    }
#pragma unroll
    for (int it = 0; it < 16; it++) {
        const int idx = (tid + it * 256) * 4;
        const int u = idx >> 7, i0 = idx & 127;
        float4 v = *(const float4*)(g_v + base + idx);
        B0[(i0 + 0) * SP + u] = v.x;
        B0[(i0 + 1) * SP + u] = v.y;
        B0[(i0 + 2) * SP + u] = v.z;
        B0[(i0 + 3) * SP + u] = v.w;
    }
    __syncthreads();

    float acc2[2][8][4];
#pragma unroll
    for (int mt = 0; mt < 2; mt++)
#pragma unroll
        for (int nt = 0; nt < 8; nt++)
#pragma unroll
            for (int r = 0; r < 4; r++) acc2[mt][nt][r] = 0.f;
    gemm3x_128(B1, B0, acc2, wm, wn, g, t4);
#pragma unroll
    for (int mt = 0; mt < 2; mt++) {
        const int r0 = wm * 32 + mt * 16 + g;
#pragma unroll
        for (int nt = 0; nt < 8; nt++) {
            const int c0 = wn * 64 + nt * 8 + 2 * t4;
            *(float2*)(g_att + base + (size_t)r0 * Mn + c0)       = make_float2(acc2[mt][nt][0], acc2[mt][nt][1]);
            *(float2*)(g_att + base + (size_t)(r0 + 8) * Mn + c0) = make_float2(acc2[mt][nt][2], acc2[mt][nt][3]);
        }
    }
    __syncthreads();

#pragma unroll
    for (int it = 0; it < 16; it++) {
        const int idx = (tid + it * 256) * 4;
        const int u = idx >> 7, j0 = idx & 127;
        const float w = LRF * dpow[127 - u];
        float4 k = *(const float4*)(g_k + base + idx);
        B1[(j0 + 0) * SP + u] = k.x * w;
        B1[(j0 + 1) * SP + u] = k.y * w;
        B1[(j0 + 2) * SP + u] = k.z * w;
        B1[(j0 + 3) * SP + u] = k.w * w;
    }
    __syncthreads();

    float acc3[2][8][4];
#pragma unroll
    for (int mt = 0; mt < 2; mt++)
#pragma unroll
        for (int nt = 0; nt < 8; nt++)
#pragma unroll
            for (int r = 0; r < 4; r++) acc3[mt][nt][r] = 0.f;
    gemm3x_128(B0, B1, acc3, wm, wn, g, t4);

    const size_t dsbase = ((size_t)b * NCn + c) * (Mn * Mn);
#pragma unroll
    for (int mt = 0; mt < 2; mt++) {
        const int r0 = wm * 32 + mt * 16 + g;
#pragma unroll
        for (int nt = 0; nt < 8; nt++) {
            const int c0 = wn * 64 + nt * 8 + 2 * t4;
            *(float2*)(g_dS + dsbase + (size_t)r0 * Mn + c0)       = make_float2(acc3[mt][nt][0], acc3[mt][nt][1]);
            *(float2*)(g_dS + dsbase + (size_t)(r0 + 8) * Mn + c0) = make_float2(acc3[mt][nt][2], acc3[mt][nt][3]);
        }
    }
}

// ===========================================================================
// K3: prefix over chunks; stores S as f16 (B operand of inter)
// ===========================================================================
__global__ void __launch_bounds__(256) scan_kernel(float* __restrict__ state_out)
{
    const int gg = blockIdx.x * blockDim.x + threadIdx.x;
    const int b  = gg >> 14;
    const int ij = gg & 16383;
    const float dc = powf(DECAYF, (float)Cn);
    float s = 0.f;
    for (int c = 0; c < NCn; c++) {
        const size_t idx = ((size_t)b * NCn + c) * 16384 + ij;
        g_S16[idx] = __float2half_rn(s);
        s = dc * s + g_dS[idx];
    }
    state_out[gg] = s;
}

// ===========================================================================
extern "C" void kernel_launch(void* const* d_in, const int* in_sizes, int n_in,
                              void* d_out, int out_size)
{
    const float* x  = (const float*)d_in[0];
    const float* Wk = (const float*)d_in[1];
    const float* bk = (const float*)d_in[2];
    const float* Wv = (const float*)d_in[3];
    const float* bv = (const float*)d_in[4];
    const float* Wq = (const float*)d_in[5];
    const float* bq = (const float*)d_in[6];
    const float* Wo = (const float*)d_in[7];
    const float* bo = (const float*)d_in[8];

    float* y         = (float*)d_out;
    float* state_out = y + (size_t)BSn * Dn;

    const int GEMM_SMEM  = 6 * STGH * 2;                     // 36864
    const int CHUNK_SMEM = (2 * 128 * SP + 128) * 4 + 512;

    cudaFuncSetAttribute(proj_kernel,    cudaFuncAttributeMaxDynamicSharedMemorySize, GEMM_SMEM);
    cudaFuncSetAttribute(outproj_kernel, cudaFuncAttributeMaxDynamicSharedMemorySize, GEMM_SMEM);
    cudaFuncSetAttribute(inter_kernel,   cudaFuncAttributeMaxDynamicSharedMemorySize, GEMM_SMEM);
    cudaFuncSetAttribute(chunk_kernel,   cudaFuncAttributeMaxDynamicSharedMemorySize, CHUNK_SMEM);

    conv_w_kernel<<<2048, 256>>>(Wk, Wv, Wq, Wo);
    proj_kernel<<<dim3(BSn / 128, 3), 256, GEMM_SMEM>>>(x, bk, bv, bq);
    chunk_kernel<<<Bn * NCn, 256, CHUNK_SMEM>>>();
    scan_kernel<<<(Bn * Mn * Mn) / 256, 256>>>(state_out);
    inter_kernel<<<Bn * NCn, 256, GEMM_SMEM>>>();
    outproj_kernel<<<dim3(BSn / 128, Dn / 128), 256, GEMM_SMEM>>>(bo, y);
}

// round 9
// speedup vs baseline: 1.5320x; 1.0926x over previous
#include <cuda_runtime.h>
#include <cuda_fp16.h>
#include <math.h>
#include <stdint.h>

// Problem constants
#define Bn   4
#define Sn   4096
#define Dn   1024
#define Mn   128
#define Cn   128
#define NCn  (Sn / Cn)
#define BSn  (Bn * Sn)
#define DECAYF 0.99f
#define LRF    0.01f

// Scratch (device globals)
__device__ __half g_kh[BSn * Mn], g_kl[BSn * Mn];
__device__ __half g_vh[BSn * Mn], g_vl[BSn * Mn];
__device__ __half g_qh[BSn * Mn], g_ql[BSn * Mn];
__device__ float  g_att[BSn * Mn];
__device__ float  g_dS [Bn * NCn * Mn * Mn];
__device__ __half g_S16[Bn * NCn * Mn * Mn];
__device__ __half g_W16[4 * 128 * 1024];          // Wk|Wv|Wq|Wo as f16

// ===========================================================================
// helpers
// ===========================================================================
__device__ __forceinline__ uint32_t smem_u32(const void* p) {
    uint32_t a;
    asm("{ .reg .u64 t; cvta.to.shared.u64 t, %1; cvt.u32.u64 %0, t; }"
        : "=r"(a) : "l"(p));
    return a;
}
__device__ __forceinline__ void splith(float v, __half& h, __half& l) {
    h = __float2half_rn(v);
    l = __float2half_rn(v - __half2float(h));
}
__device__ __forceinline__ uint32_t packh2(__half a, __half b) {
    __half2 t = __halves2half2(a, b);
    return *(uint32_t*)&t;
}
__device__ __forceinline__ void mma_f16(float* d, const uint32_t* a, const uint32_t* b) {
    asm volatile(
        "mma.sync.aligned.m16n8k16.row.col.f32.f16.f16.f32 "
        "{%0,%1,%2,%3}, {%4,%5,%6,%7}, {%8,%9}, {%0,%1,%2,%3};"
        : "+f"(d[0]), "+f"(d[1]), "+f"(d[2]), "+f"(d[3])
        : "r"(a[0]), "r"(a[1]), "r"(a[2]), "r"(a[3]), "r"(b[0]), "r"(b[1]));
}
#define CPASYNC16(sa, gp) \
    asm volatile("cp.async.ca.shared.global [%0], [%1], 16;" :: "r"(sa), "l"(gp))
#define CPCOMMIT() asm volatile("cp.async.commit_group;")
#define CPWAIT2()  asm volatile("cp.async.wait_group 2;")

extern __shared__ float sm_dyn[];

// ===========================================================================
// conv_w: weights -> f16
// ===========================================================================
__global__ void __launch_bounds__(256) conv_w_kernel(
    const float* __restrict__ Wk, const float* __restrict__ Wv,
    const float* __restrict__ Wq, const float* __restrict__ Wo)
{
    const int i = blockIdx.x * 256 + threadIdx.x;   // < 524288
    float v;
    if (i < 131072)       v = Wk[i];
    else if (i < 262144)  v = Wv[i - 131072];
    else if (i < 393216)  v = Wq[i - 262144];
    else                  v = Wo[i - 393216];
    g_W16[i] = __float2half_rn(v);
}

// ===========================================================================
// GEMM A-fp32: A fp32 (register double-buffer, cvt at staging), B f16
// (cp.async 4-stage). 256 thr, 8 warps 4x2, warp tile 32x64, K-chunk 16.
// EPI 0: fp32 C + bias.  EPI 1: hi/lo plane outputs + bias.
// smem: sA[2][3072] + sB[4][3072] halves = 36864 B.
// ===========================================================================
#define SROWH 24
#define STGH  3072

template<int EPI>
__device__ __forceinline__ void gemm_a32(
    const float* __restrict__ A, int lda,
    const __half* __restrict__ Bm, int ldb, int K,
    const float* __restrict__ bias,
    float* __restrict__ Cf, __half* __restrict__ Ch, __half* __restrict__ Cl, int ldc)
{
    __half* sA = (__half*)sm_dyn;
    __half* sB = sA + 2 * STGH;
    const uint32_t sBu = smem_u32(sB);
    const int tid = threadIdx.x;
    const int lane = tid & 31, wid = tid >> 5;
    const int wm = wid >> 1, wn = wid & 1;
    const int g = lane >> 2, t4 = lane & 3;
    const int row = tid >> 1, half = tid & 1;

    float acc[2][8][4];
#pragma unroll
    for (int mt = 0; mt < 2; mt++)
#pragma unroll
        for (int nt = 0; nt < 8; nt++)
#pragma unroll
            for (int r = 0; r < 4; r++) acc[mt][nt][r] = 0.f;

    const int nc = K >> 4;

#define ISSUE_B(ch) do { \
    const uint32_t _d = (((ch) & 3) * STGH + row * SROWH + half * 8) * 2; \
    CPASYNC16(sBu + _d, Bm + (size_t)row * ldb + (ch) * 16 + half * 8); \
} while (0)

    ISSUE_B(0); CPCOMMIT();
    ISSUE_B(1); CPCOMMIT();
    ISSUE_B(2); CPCOMMIT();

    float pre[8];
    {
        const float* ap = A + (size_t)row * lda + half * 8;
        float4 a0 = *(const float4*)ap, a1 = *(const float4*)(ap + 4);
        pre[0]=a0.x; pre[1]=a0.y; pre[2]=a0.z; pre[3]=a0.w;
        pre[4]=a1.x; pre[5]=a1.y; pre[6]=a1.z; pre[7]=a1.w;
    }

    for (int ch = 0; ch < nc; ch++) {
        {
            uint32_t w[4];
#pragma unroll
            for (int j = 0; j < 4; j++) {
                __half2 h = __floats2half2_rn(pre[2*j], pre[2*j+1]);
                w[j] = *(uint32_t*)&h;
            }
            *(uint4*)(sA + (ch & 1) * STGH + row * SROWH + half * 8) = *(uint4*)w;
        }
        if (ch + 1 < nc) {
            const float* ap = A + (size_t)row * lda + (ch + 1) * 16 + half * 8;
            float4 a0 = *(const float4*)ap, a1 = *(const float4*)(ap + 4);
            pre[0]=a0.x; pre[1]=a0.y; pre[2]=a0.z; pre[3]=a0.w;
            pre[4]=a1.x; pre[5]=a1.y; pre[6]=a1.z; pre[7]=a1.w;
        }
        CPWAIT2();
        __syncthreads();
        if (ch + 3 < nc) ISSUE_B(ch + 3);
        CPCOMMIT();

        const __half* pA = sA + (ch & 1) * STGH;
        const __half* pB = sB + (ch & 3) * STGH;

        uint32_t af[2][4];
#pragma unroll
        for (int mt = 0; mt < 2; mt++) {
            const int br = wm * 32 + mt * 16;
            af[mt][0] = *(const uint32_t*)(pA + (br + g    ) * SROWH + 2 * t4);
            af[mt][1] = *(const uint32_t*)(pA + (br + g + 8) * SROWH + 2 * t4);
            af[mt][2] = *(const uint32_t*)(pA + (br + g    ) * SROWH + 2 * t4 + 8);
            af[mt][3] = *(const uint32_t*)(pA + (br + g + 8) * SROWH + 2 * t4 + 8);
        }
#pragma unroll
        for (int nt = 0; nt < 8; nt++) {
            const int bn = wn * 64 + nt * 8 + g;
            uint32_t bf[2];
            bf[0] = *(const uint32_t*)(pB + bn * SROWH + 2 * t4);
            bf[1] = *(const uint32_t*)(pB + bn * SROWH + 2 * t4 + 8);
            mma_f16(acc[0][nt], af[0], bf);
            mma_f16(acc[1][nt], af[1], bf);
        }
    }
#undef ISSUE_B

#pragma unroll
    for (int mt = 0; mt < 2; mt++) {
        const int r0 = wm * 32 + mt * 16 + g;
#pragma unroll
        for (int nt = 0; nt < 8; nt++) {
            const int c0 = wn * 64 + nt * 8 + 2 * t4;
            const float b0 = bias ? bias[c0] : 0.f;
            const float b1 = bias ? bias[c0 + 1] : 0.f;
            float v00 = acc[mt][nt][0] + b0, v01 = acc[mt][nt][1] + b1;
            float v10 = acc[mt][nt][2] + b0, v11 = acc[mt][nt][3] + b1;
            if (EPI == 0) {
                *(float2*)(Cf + (size_t)r0 * ldc + c0)       = make_float2(v00, v01);
                *(float2*)(Cf + (size_t)(r0 + 8) * ldc + c0) = make_float2(v10, v11);
            } else {
                __half h0,l0,h1,l1;
                splith(v00, h0, l0); splith(v01, h1, l1);
                *(uint32_t*)(Ch + (size_t)r0 * ldc + c0) = packh2(h0, h1);
                *(uint32_t*)(Cl + (size_t)r0 * ldc + c0) = packh2(l0, l1);
                splith(v10, h0, l0); splith(v11, h1, l1);
                *(uint32_t*)(Ch + (size_t)(r0 + 8) * ldc + c0) = packh2(h0, h1);
                *(uint32_t*)(Cl + (size_t)(r0 + 8) * ldc + c0) = packh2(l0, l1);
            }
        }
    }
}

// ===========================================================================
// K1: projections -> hi/lo planes   grid (128, 3)
// ===========================================================================
__global__ void __launch_bounds__(256, 2) proj_kernel(
    const float* __restrict__ x,
    const float* __restrict__ bk, const float* __restrict__ bv,
    const float* __restrict__ bq)
{
    const size_t rb = (size_t)blockIdx.x * 128;
    const int yv = blockIdx.y;
    const float* bias = (yv == 0) ? bk : (yv == 1) ? bv : bq;
    __half* Ch = (yv == 0) ? g_kh : (yv == 1) ? g_vh : g_qh;
    __half* Cl = (yv == 0) ? g_kl : (yv == 1) ? g_vl : g_ql;
    gemm_a32<1>(x + rb * Dn, Dn, g_W16 + (size_t)yv * 131072, Dn, Dn,
                bias, nullptr, Ch + rb * Mn, Cl + rb * Mn, Mn);
}

// ===========================================================================
// K5: y = att @ Wo^T + bo   grid (128, 8)
// ===========================================================================
__global__ void __launch_bounds__(256, 2) outproj_kernel(
    const float* __restrict__ bo, float* __restrict__ y)
{
    const size_t rb = (size_t)blockIdx.x * 128;
    const int    cb = blockIdx.y * 128;
    gemm_a32<0>(g_att + rb * Mn, Mn, g_W16 + 393216 + (size_t)cb * Mn, Mn, Mn,
                bo + cb, y + rb * Dn + cb, nullptr, nullptr, Dn);
}

// ===========================================================================
// K4: inter — both operands f16 via cp.async (A = qh plane, B = S16).
// att[t][i] += decay^t * sum_j S[i][j] q[t][j].  grid 128.
// smem: sA[4][3072] + sB[4][3072] halves = 49152 B.
// ===========================================================================
__global__ void __launch_bounds__(256, 2) inter_kernel()
{
    __half* sA = (__half*)sm_dyn;
    __half* sB = sA + 4 * STGH;
    const uint32_t sAu = smem_u32(sA), sBu = smem_u32(sB);
    const int tid = threadIdx.x;
    const int lane = tid & 31, wid = tid >> 5;
    const int wm = wid >> 1, wn = wid & 1;
    const int g = lane >> 2, t4 = lane & 3;
    const int row = tid >> 1, half = tid & 1;

    const int b = blockIdx.x / NCn;
    const int c = blockIdx.x % NCn;
    const size_t base  = ((size_t)b * Sn + (size_t)c * Cn) * Mn;
    const size_t sbase = ((size_t)b * NCn + c) * 16384;
    const __half* A = g_qh + base;
    const __half* Bm = g_S16 + sbase;

    float acc[2][8][4];
#pragma unroll
    for (int mt = 0; mt < 2; mt++)
#pragma unroll
        for (int nt = 0; nt < 8; nt++)
#pragma unroll
            for (int r = 0; r < 4; r++) acc[mt][nt][r] = 0.f;

#define ISSUE2(ch) do { \
    const uint32_t _d = (((ch) & 3) * STGH + row * SROWH + half * 8) * 2; \
    const size_t _s = (size_t)row * Mn + (ch) * 16 + half * 8; \
    CPASYNC16(sAu + _d, A + _s); \
    CPASYNC16(sBu + _d, Bm + _s); \
} while (0)

    ISSUE2(0); CPCOMMIT();
    ISSUE2(1); CPCOMMIT();
    ISSUE2(2); CPCOMMIT();

    for (int ch = 0; ch < 8; ch++) {
        CPWAIT2();
        __syncthreads();
        if (ch + 3 < 8) ISSUE2(ch + 3);
        CPCOMMIT();

        const __half* pA = sA + (ch & 3) * STGH;
        const __half* pB = sB + (ch & 3) * STGH;

        uint32_t af[2][4];
#pragma unroll
        for (int mt = 0; mt < 2; mt++) {
            const int br = wm * 32 + mt * 16;
            af[mt][0] = *(const uint32_t*)(pA + (br + g    ) * SROWH + 2 * t4);
            af[mt][1] = *(const uint32_t*)(pA + (br + g + 8) * SROWH + 2 * t4);
            af[mt][2] = *(const uint32_t*)(pA + (br + g    ) * SROWH + 2 * t4 + 8);
            af[mt][3] = *(const uint32_t*)(pA + (br + g + 8) * SROWH + 2 * t4 + 8);
        }
#pragma unroll
        for (int nt = 0; nt < 8; nt++) {
            const int bn = wn * 64 + nt * 8 + g;
            uint32_t bf[2];
            bf[0] = *(const uint32_t*)(pB + bn * SROWH + 2 * t4);
            bf[1] = *(const uint32_t*)(pB + bn * SROWH + 2 * t4 + 8);
            mma_f16(acc[0][nt], af[0], bf);
            mma_f16(acc[1][nt], af[1], bf);
        }
    }
#undef ISSUE2

#pragma unroll
    for (int mt = 0; mt < 2; mt++) {
        const int r0 = wm * 32 + mt * 16 + g;
        const float f0 = powf(DECAYF, (float)r0);
        const float f1 = powf(DECAYF, (float)(r0 + 8));
#pragma unroll
        for (int nt = 0; nt < 8; nt++) {
            const int c0 = wn * 64 + nt * 8 + 2 * t4;
            float2* p0 = (float2*)(g_att + base + (size_t)r0 * Mn + c0);
            float2* p1 = (float2*)(g_att + base + (size_t)(r0 + 8) * Mn + c0);
            float2 o0 = *p0, o1 = *p1;
            o0.x += f0 * acc[mt][nt][0]; o0.y += f0 * acc[mt][nt][1];
            o1.x += f1 * acc[mt][nt][2]; o1.y += f1 * acc[mt][nt][3];
            *p0 = o0; *p1 = o1;
        }
    }
}

// ===========================================================================
// K2: chunk — fp16 hi/lo 2-plane compensated, three 128^3 GEMMs on resident
// smem planes. grid 128, 256 thr. smem ~209.4 KB.
// ===========================================================================
#define CP 136
#define CPL (128 * CP)

__device__ __forceinline__ void gemm_sm_f16(
    const __half* __restrict__ Ah, const __half* __restrict__ Al,
    const __half* __restrict__ Bh, const __half* __restrict__ Bl,
    float acc[2][8][4], int wm, int wn, int g, int t4)
{
#pragma unroll
    for (int kk = 0; kk < 8; kk++) {
        const int ko = kk * 16;
        uint32_t ah[2][4], al[2][4];
#pragma unroll
        for (int mt = 0; mt < 2; mt++) {
            const int br = wm * 32 + mt * 16;
            ah[mt][0] = *(const uint32_t*)(Ah + (br + g    ) * CP + ko + 2 * t4);
            ah[mt][1] = *(const uint32_t*)(Ah + (br + g + 8) * CP + ko + 2 * t4);
            ah[mt][2] = *(const uint32_t*)(Ah + (br + g    ) * CP + ko + 2 * t4 + 8);
            ah[mt][3] = *(const uint32_t*)(Ah + (br + g + 8) * CP + ko + 2 * t4 + 8);
            al[mt][0] = *(const uint32_t*)(Al + (br + g    ) * CP + ko + 2 * t4);
            al[mt][1] = *(const uint32_t*)(Al + (br + g + 8) * CP + ko + 2 * t4);
            al[mt][2] = *(const uint32_t*)(Al + (br + g    ) * CP + ko + 2 * t4 + 8);
            al[mt][3] = *(const uint32_t*)(Al + (br + g + 8) * CP + ko + 2 * t4 + 8);
        }
#pragma unroll
        for (int nt = 0; nt < 8; nt++) {
            const int bn = wn * 64 + nt * 8 + g;
            uint32_t bh[2], bl[2];
            bh[0] = *(const uint32_t*)(Bh + bn * CP + ko + 2 * t4);
            bh[1] = *(const uint32_t*)(Bh + bn * CP + ko + 2 * t4 + 8);
            bl[0] = *(const uint32_t*)(Bl + bn * CP + ko + 2 * t4);
            bl[1] = *(const uint32_t*)(Bl + bn * CP + ko + 2 * t4 + 8);
#pragma unroll
            for (int mt = 0; mt < 2; mt++) {
                mma_f16(acc[mt][nt], ah[mt], bh);
                mma_f16(acc[mt][nt], al[mt], bh);
                mma_f16(acc[mt][nt], ah[mt], bl);
            }
        }
    }
}

__global__ void __launch_bounds__(256) chunk_kernel()
{
    __half* Qh  = (__half*)sm_dyn;      // -> S planes -> Ktw planes
    __half* Ql  = Qh + CPL;
    __half* Kh  = Qh + 2 * CPL;
    __half* Kl  = Qh + 3 * CPL;
    __half* Vth = Qh + 4 * CPL;
    __half* Vtl = Qh + 5 * CPL;
    float* dpow = (float*)(Qh + 6 * CPL);

    const uint32_t uQh = smem_u32(Qh);
    const int tid = threadIdx.x;
    const int lane = tid & 31, wid = tid >> 5;
    const int wm = wid >> 1, wn = wid & 1;
    const int g = lane >> 2, t4 = lane & 3;
    const int b = blockIdx.x / NCn;
    const int c = blockIdx.x % NCn;
    const size_t base = ((size_t)b * Sn + (size_t)c * Cn) * Mn;

    // cp.async q,k planes (natural layout, padded stride)
#pragma unroll
    for (int it = 0; it < 8; it++) {
        const int sid = tid + it * 256;       // 0..2047
        const int u = sid >> 4, seg = sid & 15;
        const uint32_t dof = (u * CP + seg * 8) * 2;
        const size_t sof = base + (size_t)u * Mn + seg * 8;
        CPASYNC16(uQh + dof,               g_qh + sof);
        CPASYNC16(uQh + CPL * 2 + dof,     g_ql + sof);
        CPASYNC16(uQh + 2 * CPL * 2 + dof, g_kh + sof);
        CPASYNC16(uQh + 3 * CPL * 2 + dof, g_kl + sof);
    }
    CPCOMMIT();

    if (tid < 128) dpow[tid] = powf(DECAYF, (float)tid);

    // V^T planes (scatter transpose from gmem)
#pragma unroll
    for (int it = 0; it < 8; it++) {
        const int task = tid + it * 256;
        const int u = task & 127, i0 = (task >> 7) * 8;
        uint4 dh = *(const uint4*)(g_vh + base + (size_t)u * Mn + i0);
        uint4 dl = *(const uint4*)(g_vl + base + (size_t)u * Mn + i0);
        const __half* ph = (const __half*)&dh;
        const __half* pl = (const __half*)&dl;
#pragma unroll
        for (int j = 0; j < 8; j++) {
            Vth[(i0 + j) * CP + u] = ph[j];
            Vtl[(i0 + j) * CP + u] = pl[j];
        }
    }

    asm volatile("cp.async.wait_group 0;");
    __syncthreads();

    // GEMM1: S[t][u] = q_t . k_u
    float acc[2][8][4];
#pragma unroll
    for (int mt = 0; mt < 2; mt++)
#pragma unroll
        for (int nt = 0; nt < 8; nt++)
#pragma unroll
            for (int r = 0; r < 4; r++) acc[mt][nt][r] = 0.f;
    gemm_sm_f16(Qh, Ql, Kh, Kl, acc, wm, wn, g, t4);

#pragma unroll
    for (int mt = 0; mt < 2; mt++)
#pragma unroll
        for (int nt = 0; nt < 8; nt++)
#pragma unroll
            for (int r = 0; r < 4; r++) {
                const int t = wm * 32 + mt * 16 + g + ((r >= 2) ? 8 : 0);
                const int u = wn * 64 + nt * 8 + 2 * t4 + (r & 1);
                acc[mt][nt][r] = (u < t) ? acc[mt][nt][r] * (LRF * dpow[t - 1 - u]) : 0.f;
            }
    __syncthreads();

    // S planes over Q area
#pragma unroll
    for (int mt = 0; mt < 2; mt++) {
        const int r0 = wm * 32 + mt * 16 + g;
#pragma unroll
        for (int nt = 0; nt < 8; nt++) {
            const int c0 = wn * 64 + nt * 8 + 2 * t4;
            __half h0,l0,h1,l1;
            splith(acc[mt][nt][0], h0, l0); splith(acc[mt][nt][1], h1, l1);
            *(uint32_t*)(Qh + r0 * CP + c0) = packh2(h0, h1);
            *(uint32_t*)(Ql + r0 * CP + c0) = packh2(l0, l1);
            splith(acc[mt][nt][2], h0, l0); splith(acc[mt][nt][3], h1, l1);
            *(uint32_t*)(Qh + (r0 + 8) * CP + c0) = packh2(h0, h1);
            *(uint32_t*)(Ql + (r0 + 8) * CP + c0) = packh2(l0, l1);
        }
    }
    __syncthreads();

    // GEMM2: out[t][i] = S x V^T -> g_att
    float acc2[2][8][4];
#pragma unroll
    for (int mt = 0; mt < 2; mt++)
#pragma unroll
        for (int nt = 0; nt < 8; nt++)
#pragma unroll
            for (int r = 0; r < 4; r++) acc2[mt][nt][r] = 0.f;
    gemm_sm_f16(Qh, Ql, Vth, Vtl, acc2, wm, wn, g, t4);
#pragma unroll
    for (int mt = 0; mt < 2; mt++) {
        const int r0 = wm * 32 + mt * 16 + g;
#pragma unroll
        for (int nt = 0; nt < 8; nt++) {
            const int c0 = wn * 64 + nt * 8 + 2 * t4;
            *(float2*)(g_att + base + (size_t)r0 * Mn + c0)       = make_float2(acc2[mt][nt][0], acc2[mt][nt][1]);
            *(float2*)(g_att + base + (size_t)(r0 + 8) * Mn + c0) = make_float2(acc2[mt][nt][2], acc2[mt][nt][3]);
        }
    }
    __syncthreads();

    // Ktw planes over Q/S area: Ktw[j][u] = k[u][j] * lr*decay^(127-u)
#pragma unroll
    for (int it = 0; it < 8; it++) {
        const int task = tid + it * 256;
        const int u = task & 127, j0 = (task >> 7) * 8;
        const float w = LRF * dpow[127 - u];
#pragma unroll
        for (int j = 0; j < 8; j++) {
            float f = (__half2float(Kh[u * CP + j0 + j]) +
                       __half2float(Kl[u * CP + j0 + j])) * w;
            __half h, l; splith(f, h, l);
            Qh[(j0 + j) * CP + u] = h;
            Ql[(j0 + j) * CP + u] = l;
        }
    }
    __syncthreads();

    // GEMM3: dS[i][j] = V^T x Ktw -> g_dS
    float acc3[2][8][4];
#pragma unroll
    for (int mt = 0; mt < 2; mt++)
#pragma unroll
        for (int nt = 0; nt < 8; nt++)
#pragma unroll
            for (int r = 0; r < 4; r++) acc3[mt][nt][r] = 0.f;
    gemm_sm_f16(Vth, Vtl, Qh, Ql, acc3, wm, wn, g, t4);

    const size_t dsbase = ((size_t)b * NCn + c) * (Mn * Mn);
#pragma unroll
    for (int mt = 0; mt < 2; mt++) {
        const int r0 = wm * 32 + mt * 16 + g;
#pragma unroll
        for (int nt = 0; nt < 8; nt++) {
            const int c0 = wn * 64 + nt * 8 + 2 * t4;
            *(float2*)(g_dS + dsbase + (size_t)r0 * Mn + c0)       = make_float2(acc3[mt][nt][0], acc3[mt][nt][1]);
            *(float2*)(g_dS + dsbase + (size_t)(r0 + 8) * Mn + c0) = make_float2(acc3[mt][nt][2], acc3[mt][nt][3]);
        }
    }
}

// ===========================================================================
// K3: prefix over chunks, vectorized x4 (MLP=4)
// ===========================================================================
__global__ void __launch_bounds__(256) scan_kernel(float* __restrict__ state_out)
{
    const int gg = blockIdx.x * blockDim.x + threadIdx.x;  // 0..16383
    const int b   = gg >> 12;
    const int ij0 = (gg & 4095) * 4;
    const float dc = powf(DECAYF, (float)Cn);
    float4 s = make_float4(0.f, 0.f, 0.f, 0.f);
    for (int c = 0; c < NCn; c++) {
        const size_t idx = ((size_t)b * NCn + c) * 16384 + ij0;
        float4 d = *(const float4*)(g_dS + idx);
        __half2 h0 = __floats2half2_rn(s.x, s.y);
        __half2 h1 = __floats2half2_rn(s.z, s.w);
        *(uint32_t*)(g_S16 + idx)     = *(uint32_t*)&h0;
        *(uint32_t*)(g_S16 + idx + 2) = *(uint32_t*)&h1;
        s.x = dc * s.x + d.x; s.y = dc * s.y + d.y;
        s.z = dc * s.z + d.z; s.w = dc * s.w + d.w;
    }
    *(float4*)(state_out + (size_t)b * 16384 + ij0) = s;
}

// ===========================================================================
extern "C" void kernel_launch(void* const* d_in, const int* in_sizes, int n_in,
                              void* d_out, int out_size)
{
    const float* x  = (const float*)d_in[0];
    const float* Wk = (const float*)d_in[1];
    const float* bk = (const float*)d_in[2];
    const float* Wv = (const float*)d_in[3];
    const float* bv = (const float*)d_in[4];
    const float* Wq = (const float*)d_in[5];
    const float* bq = (const float*)d_in[6];
    const float* Wo = (const float*)d_in[7];
    const float* bo = (const float*)d_in[8];

    float* y         = (float*)d_out;
    float* state_out = y + (size_t)BSn * Dn;

    const int A32_SMEM   = 6 * STGH * 2;        // 36864
    const int INTER_SMEM = 8 * STGH * 2;        // 49152
    const int CHUNK_SMEM = 6 * CPL * 2 + 512;   // 209408

    cudaFuncSetAttribute(proj_kernel,    cudaFuncAttributeMaxDynamicSharedMemorySize, A32_SMEM);
    cudaFuncSetAttribute(outproj_kernel, cudaFuncAttributeMaxDynamicSharedMemorySize, A32_SMEM);
    cudaFuncSetAttribute(inter_kernel,   cudaFuncAttributeMaxDynamicSharedMemorySize, INTER_SMEM);
    cudaFuncSetAttribute(chunk_kernel,   cudaFuncAttributeMaxDynamicSharedMemorySize, CHUNK_SMEM);

    conv_w_kernel<<<2048, 256>>>(Wk, Wv, Wq, Wo);
    proj_kernel<<<dim3(BSn / 128, 3), 256, A32_SMEM>>>(x, bk, bv, bq);
    chunk_kernel<<<Bn * NCn, 256, CHUNK_SMEM>>>();
    scan_kernel<<<64, 256>>>(state_out);
    inter_kernel<<<Bn * NCn, 256, INTER_SMEM>>>();
    outproj_kernel<<<dim3(BSn / 128, Dn / 128), 256, A32_SMEM>>>(bo, y);
}

// round 10
// speedup vs baseline: 1.6412x; 1.0713x over previous
#include <cuda_runtime.h>
#include <cuda_fp16.h>
#include <math.h>
#include <stdint.h>

// Problem constants
#define Bn   4
#define Sn   4096
#define Dn   1024
#define Mn   128
#define Cn   128
#define NCn  (Sn / Cn)
#define BSn  (Bn * Sn)
#define DECAYF 0.99f
#define LRF    0.01f

// Scratch (device globals)
__device__ __half g_kh[BSn * Mn], g_kl[BSn * Mn];
__device__ __half g_vh[BSn * Mn], g_vl[BSn * Mn];
__device__ __half g_qh[BSn * Mn], g_ql[BSn * Mn];
__device__ float  g_att[BSn * Mn];               // intra part only
__device__ float  g_dS [Bn * NCn * Mn * Mn];
__device__ __half g_S16[Bn * NCn * Mn * Mn];
__device__ __half g_W16[4 * 128 * 1024];         // Wk|Wv|Wq|Wo as f16

// ===========================================================================
// helpers
// ===========================================================================
__device__ __forceinline__ uint32_t smem_u32(const void* p) {
    uint32_t a;
    asm("{ .reg .u64 t; cvta.to.shared.u64 t, %1; cvt.u32.u64 %0, t; }"
        : "=r"(a) : "l"(p));
    return a;
}
__device__ __forceinline__ void splith(float v, __half& h, __half& l) {
    h = __float2half_rn(v);
    l = __float2half_rn(v - __half2float(h));
}
__device__ __forceinline__ uint32_t packh2(__half a, __half b) {
    __half2 t = __halves2half2(a, b);
    return *(uint32_t*)&t;
}
__device__ __forceinline__ void mma_f16(float* d, const uint32_t* a, const uint32_t* b) {
    asm volatile(
        "mma.sync.aligned.m16n8k16.row.col.f32.f16.f16.f32 "
        "{%0,%1,%2,%3}, {%4,%5,%6,%7}, {%8,%9}, {%0,%1,%2,%3};"
        : "+f"(d[0]), "+f"(d[1]), "+f"(d[2]), "+f"(d[3])
        : "r"(a[0]), "r"(a[1]), "r"(a[2]), "r"(a[3]), "r"(b[0]), "r"(b[1]));
}
#define CPASYNC16(sa, gp) \
    asm volatile("cp.async.ca.shared.global [%0], [%1], 16;" :: "r"(sa), "l"(gp))
#define CPCOMMIT() asm volatile("cp.async.commit_group;")
#define CPWAIT2()  asm volatile("cp.async.wait_group 2;")
#define CPWAIT0()  asm volatile("cp.async.wait_group 0;")

extern __shared__ float sm_dyn[];

// ===========================================================================
// conv_w: weights -> f16
// ===========================================================================
__global__ void __launch_bounds__(256) conv_w_kernel(
    const float* __restrict__ Wk, const float* __restrict__ Wv,
    const float* __restrict__ Wq, const float* __restrict__ Wo)
{
    const int i = blockIdx.x * 256 + threadIdx.x;   // < 524288
    float v;
    if (i < 131072)       v = Wk[i];
    else if (i < 262144)  v = Wv[i - 131072];
    else if (i < 393216)  v = Wq[i - 262144];
    else                  v = Wo[i - 393216];
    g_W16[i] = __float2half_rn(v);
}

// ===========================================================================
// GEMM A-fp32 (proj): A fp32 reg-prefetch + cvt at staging, B f16 cp.async.
// 256 thr, 8 warps 4x2, warp tile 32x64, K-chunk 16. Outputs hi/lo planes.
// smem: sA[2][3072] + sB[4][3072] halves = 36864 B.
// ===========================================================================
#define SROWH 24
#define STGH  3072

__device__ __forceinline__ void gemm_proj(
    const float* __restrict__ A, int lda,
    const __half* __restrict__ Bm, int ldb, int K,
    const float* __restrict__ bias,
    __half* __restrict__ Ch, __half* __restrict__ Cl, int ldc)
{
    __half* sA = (__half*)sm_dyn;
    __half* sB = sA + 2 * STGH;
    const uint32_t sBu = smem_u32(sB);
    const int tid = threadIdx.x;
    const int lane = tid & 31, wid = tid >> 5;
    const int wm = wid >> 1, wn = wid & 1;
    const int g = lane >> 2, t4 = lane & 3;
    const int row = tid >> 1, half = tid & 1;

    float acc[2][8][4];
#pragma unroll
    for (int mt = 0; mt < 2; mt++)
#pragma unroll
        for (int nt = 0; nt < 8; nt++)
#pragma unroll
            for (int r = 0; r < 4; r++) acc[mt][nt][r] = 0.f;

    const int nc = K >> 4;

#define ISSUE_B(ch) do { \
    const uint32_t _d = (((ch) & 3) * STGH + row * SROWH + half * 8) * 2; \
    CPASYNC16(sBu + _d, Bm + (size_t)row * ldb + (ch) * 16 + half * 8); \
} while (0)

    ISSUE_B(0); CPCOMMIT();
    ISSUE_B(1); CPCOMMIT();
    ISSUE_B(2); CPCOMMIT();

    float pre[8];
    {
        const float* ap = A + (size_t)row * lda + half * 8;
        float4 a0 = *(const float4*)ap, a1 = *(const float4*)(ap + 4);
        pre[0]=a0.x; pre[1]=a0.y; pre[2]=a0.z; pre[3]=a0.w;
        pre[4]=a1.x; pre[5]=a1.y; pre[6]=a1.z; pre[7]=a1.w;
    }

    for (int ch = 0; ch < nc; ch++) {
        {
            uint32_t w[4];
#pragma unroll
            for (int j = 0; j < 4; j++) {
                __half2 h = __floats2half2_rn(pre[2*j], pre[2*j+1]);
                w[j] = *(uint32_t*)&h;
            }
            *(uint4*)(sA + (ch & 1) * STGH + row * SROWH + half * 8) = *(uint4*)w;
        }
        if (ch + 1 < nc) {
            const float* ap = A + (size_t)row * lda + (ch + 1) * 16 + half * 8;
            float4 a0 = *(const float4*)ap, a1 = *(const float4*)(ap + 4);
            pre[0]=a0.x; pre[1]=a0.y; pre[2]=a0.z; pre[3]=a0.w;
            pre[4]=a1.x; pre[5]=a1.y; pre[6]=a1.z; pre[7]=a1.w;
        }
        CPWAIT2();
        __syncthreads();
        if (ch + 3 < nc) ISSUE_B(ch + 3);
        CPCOMMIT();

        const __half* pA = sA + (ch & 1) * STGH;
        const __half* pB = sB + (ch & 3) * STGH;

        uint32_t af[2][4];
#pragma unroll
        for (int mt = 0; mt < 2; mt++) {
            const int br = wm * 32 + mt * 16;
            af[mt][0] = *(const uint32_t*)(pA + (br + g    ) * SROWH + 2 * t4);
            af[mt][1] = *(const uint32_t*)(pA + (br + g + 8) * SROWH + 2 * t4);
            af[mt][2] = *(const uint32_t*)(pA + (br + g    ) * SROWH + 2 * t4 + 8);
            af[mt][3] = *(const uint32_t*)(pA + (br + g + 8) * SROWH + 2 * t4 + 8);
        }
#pragma unroll
        for (int nt = 0; nt < 8; nt++) {
            const int bn = wn * 64 + nt * 8 + g;
            uint32_t bf[2];
            bf[0] = *(const uint32_t*)(pB + bn * SROWH + 2 * t4);
            bf[1] = *(const uint32_t*)(pB + bn * SROWH + 2 * t4 + 8);
            mma_f16(acc[0][nt], af[0], bf);
            mma_f16(acc[1][nt], af[1], bf);
        }
    }
#undef ISSUE_B

#pragma unroll
    for (int mt = 0; mt < 2; mt++) {
        const int r0 = wm * 32 + mt * 16 + g;
#pragma unroll
        for (int nt = 0; nt < 8; nt++) {
            const int c0 = wn * 64 + nt * 8 + 2 * t4;
            const float b0 = bias[c0], b1 = bias[c0 + 1];
            float v00 = acc[mt][nt][0] + b0, v01 = acc[mt][nt][1] + b1;
            float v10 = acc[mt][nt][2] + b0, v11 = acc[mt][nt][3] + b1;
            __half h0,l0,h1,l1;
            splith(v00, h0, l0); splith(v01, h1, l1);
            *(uint32_t*)(Ch + (size_t)r0 * ldc + c0) = packh2(h0, h1);
            *(uint32_t*)(Cl + (size_t)r0 * ldc + c0) = packh2(l0, l1);
            splith(v10, h0, l0); splith(v11, h1, l1);
            *(uint32_t*)(Ch + (size_t)(r0 + 8) * ldc + c0) = packh2(h0, h1);
            *(uint32_t*)(Cl + (size_t)(r0 + 8) * ldc + c0) = packh2(l0, l1);
        }
    }
}

// ===========================================================================
// K1: projections -> hi/lo planes   grid (128, 3)
// ===========================================================================
__global__ void __launch_bounds__(256, 2) proj_kernel(
    const float* __restrict__ x,
    const float* __restrict__ bk, const float* __restrict__ bv,
    const float* __restrict__ bq)
{
    const size_t rb = (size_t)blockIdx.x * 128;
    const int yv = blockIdx.y;
    const float* bias = (yv == 0) ? bk : (yv == 1) ? bv : bq;
    __half* Ch = (yv == 0) ? g_kh : (yv == 1) ? g_vh : g_qh;
    __half* Cl = (yv == 0) ? g_kl : (yv == 1) ? g_vl : g_ql;
    gemm_proj(x + rb * Dn, Dn, g_W16 + (size_t)yv * 131072, Dn, Dn,
              bias, Ch + rb * Mn, Cl + rb * Mn, Mn);
}

// ===========================================================================
// K4+K5 fused: per (b,c) block:
//   stage 1: inter = q x S^T (f16 cp.async), att_tile = g_att + decay^t*inter
//            -> fp16 smem tile
//   stage 2: y[128, 1024] = att_tile x Wo^T + bo (8 col-tiles, cp.async ring)
// smem: ring 8*3072 halves (49152 B) + sAtt 128*136 halves (34816 B) = 83968 B
// ===========================================================================
#define AP 136

__global__ void __launch_bounds__(256) fuse_out_kernel(
    const float* __restrict__ bo, float* __restrict__ y)
{
    __half* sQ   = (__half*)sm_dyn;        // stage-1 A ring (4) ; stage-2 W ring (4)
    __half* sS   = sQ + 4 * STGH;          // stage-1 B ring (4)
    __half* sAtt = sQ + 8 * STGH;          // 128 x AP
    const uint32_t uQ = smem_u32(sQ), uS = smem_u32(sS);
    const int tid = threadIdx.x;
    const int lane = tid & 31, wid = tid >> 5;
    const int wm = wid >> 1, wn = wid & 1;
    const int g = lane >> 2, t4 = lane & 3;
    const int row = tid >> 1, half = tid & 1;

    const int b = blockIdx.x / NCn;
    const int c = blockIdx.x % NCn;
    const size_t base  = ((size_t)b * Sn + (size_t)c * Cn) * Mn;
    const size_t sbase = ((size_t)b * NCn + c) * 16384;
    const __half* Aq = g_qh + base;
    const __half* Bs = g_S16 + sbase;

    // ---------------- stage 1: inter GEMM ----------------
    float acc[2][8][4];
#pragma unroll
    for (int mt = 0; mt < 2; mt++)
#pragma unroll
        for (int nt = 0; nt < 8; nt++)
#pragma unroll
            for (int r = 0; r < 4; r++) acc[mt][nt][r] = 0.f;

#define ISSUE1(ch) do { \
    const uint32_t _d = (((ch) & 3) * STGH + row * SROWH + half * 8) * 2; \
    const size_t _s = (size_t)row * Mn + (ch) * 16 + half * 8; \
    CPASYNC16(uQ + _d, Aq + _s); \
    CPASYNC16(uS + _d, Bs + _s); \
} while (0)

    ISSUE1(0); CPCOMMIT();
    ISSUE1(1); CPCOMMIT();
    ISSUE1(2); CPCOMMIT();

    for (int ch = 0; ch < 8; ch++) {
        CPWAIT2();
        __syncthreads();
        if (ch + 3 < 8) ISSUE1(ch + 3);
        CPCOMMIT();

        const __half* pA = sQ + (ch & 3) * STGH;
        const __half* pB = sS + (ch & 3) * STGH;

        uint32_t af[2][4];
#pragma unroll
        for (int mt = 0; mt < 2; mt++) {
            const int br = wm * 32 + mt * 16;
            af[mt][0] = *(const uint32_t*)(pA + (br + g    ) * SROWH + 2 * t4);
            af[mt][1] = *(const uint32_t*)(pA + (br + g + 8) * SROWH + 2 * t4);
            af[mt][2] = *(const uint32_t*)(pA + (br + g    ) * SROWH + 2 * t4 + 8);
            af[mt][3] = *(const uint32_t*)(pA + (br + g + 8) * SROWH + 2 * t4 + 8);
        }
#pragma unroll
        for (int nt = 0; nt < 8; nt++) {
            const int bn = wn * 64 + nt * 8 + g;
            uint32_t bf[2];
            bf[0] = *(const uint32_t*)(pB + bn * SROWH + 2 * t4);
            bf[1] = *(const uint32_t*)(pB + bn * SROWH + 2 * t4 + 8);
            mma_f16(acc[0][nt], af[0], bf);
            mma_f16(acc[1][nt], af[1], bf);
        }
    }
#undef ISSUE1

    CPWAIT0();
    __syncthreads();

    // epilogue: att = intra (fp32) + decay^t * inter -> fp16 tile
#pragma unroll
    for (int mt = 0; mt < 2; mt++) {
        const int r0 = wm * 32 + mt * 16 + g;
        const float f0 = powf(DECAYF, (float)r0);
        const float f1 = powf(DECAYF, (float)(r0 + 8));
#pragma unroll
        for (int nt = 0; nt < 8; nt++) {
            const int c0 = wn * 64 + nt * 8 + 2 * t4;
            float2 i0v = *(const float2*)(g_att + base + (size_t)r0 * Mn + c0);
            float2 i1v = *(const float2*)(g_att + base + (size_t)(r0 + 8) * Mn + c0);
            __half2 h0 = __floats2half2_rn(i0v.x + f0 * acc[mt][nt][0],
                                           i0v.y + f0 * acc[mt][nt][1]);
            __half2 h1 = __floats2half2_rn(i1v.x + f1 * acc[mt][nt][2],
                                           i1v.y + f1 * acc[mt][nt][3]);
            *(uint32_t*)(sAtt + r0 * AP + c0)       = *(uint32_t*)&h0;
            *(uint32_t*)(sAtt + (r0 + 8) * AP + c0) = *(uint32_t*)&h1;
        }
    }
    __syncthreads();

    // ---------------- stage 2: y = att x Wo^T + bo ----------------
    const __half* Wo = g_W16 + 393216;
    const size_t yrow = (size_t)b * Sn + (size_t)c * Cn;

#define ISSUE_W(m) do { \
    const int _cb = (m) >> 3, _kc = (m) & 7; \
    const uint32_t _d = (((m) & 3) * STGH + row * SROWH + half * 8) * 2; \
    CPASYNC16(uQ + _d, Wo + (size_t)(_cb * 128 + row) * Mn + _kc * 16 + half * 8); \
} while (0)

    ISSUE_W(0); CPCOMMIT();
    ISSUE_W(1); CPCOMMIT();
    ISSUE_W(2); CPCOMMIT();

    float acy[2][8][4];
    for (int m = 0; m < 64; m++) {
        const int cb = m >> 3, kc = m & 7;
        if (kc == 0) {
#pragma unroll
            for (int mt = 0; mt < 2; mt++)
#pragma unroll
                for (int nt = 0; nt < 8; nt++)
#pragma unroll
                    for (int r = 0; r < 4; r++) acy[mt][nt][r] = 0.f;
        }
        CPWAIT2();
        __syncthreads();
        if (m + 3 < 64) ISSUE_W(m + 3);
        CPCOMMIT();

        const __half* pW = sQ + (m & 3) * STGH;
        const int ko = kc * 16;

        uint32_t af[2][4];
#pragma unroll
        for (int mt = 0; mt < 2; mt++) {
            const int br = wm * 32 + mt * 16;
            af[mt][0] = *(const uint32_t*)(sAtt + (br + g    ) * AP + ko + 2 * t4);
            af[mt][1] = *(const uint32_t*)(sAtt + (br + g + 8) * AP + ko + 2 * t4);
            af[mt][2] = *(const uint32_t*)(sAtt + (br + g    ) * AP + ko + 2 * t4 + 8);
            af[mt][3] = *(const uint32_t*)(sAtt + (br + g + 8) * AP + ko + 2 * t4 + 8);
        }
#pragma unroll
        for (int nt = 0; nt < 8; nt++) {
            const int bn = wn * 64 + nt * 8 + g;
            uint32_t bf[2];
            bf[0] = *(const uint32_t*)(pW + bn * SROWH + 2 * t4);
            bf[1] = *(const uint32_t*)(pW + bn * SROWH + 2 * t4 + 8);
            mma_f16(acy[0][nt], af[0], bf);
            mma_f16(acy[1][nt], af[1], bf);
        }

        if (kc == 7) {
#pragma unroll
            for (int mt = 0; mt < 2; mt++) {
                const int r0 = wm * 32 + mt * 16 + g;
#pragma unroll
                for (int nt = 0; nt < 8; nt++) {
                    const int c0 = wn * 64 + nt * 8 + 2 * t4;
                    const float b0 = bo[cb * 128 + c0], b1 = bo[cb * 128 + c0 + 1];
                    *(float2*)(y + (yrow + r0) * Dn + cb * 128 + c0) =
                        make_float2(acy[mt][nt][0] + b0, acy[mt][nt][1] + b1);
                    *(float2*)(y + (yrow + r0 + 8) * Dn + cb * 128 + c0) =
                        make_float2(acy[mt][nt][2] + b0, acy[mt][nt][3] + b1);
                }
            }
        }
    }
#undef ISSUE_W
}

// ===========================================================================
// K2: chunk — fp16 hi/lo 2-plane compensated, three 128^3 GEMMs on resident
// smem planes. grid 128, 256 thr. smem ~209.4 KB.
// ===========================================================================
#define CP 136
#define CPL (128 * CP)

__device__ __forceinline__ void gemm_sm_f16(
    const __half* __restrict__ Ah, const __half* __restrict__ Al,
    const __half* __restrict__ Bh, const __half* __restrict__ Bl,
    float acc[2][8][4], int wm, int wn, int g, int t4)
{
#pragma unroll
    for (int kk = 0; kk < 8; kk++) {
        const int ko = kk * 16;
        uint32_t ah[2][4], al[2][4];
#pragma unroll
        for (int mt = 0; mt < 2; mt++) {
            const int br = wm * 32 + mt * 16;
            ah[mt][0] = *(const uint32_t*)(Ah + (br + g    ) * CP + ko + 2 * t4);
            ah[mt][1] = *(const uint32_t*)(Ah + (br + g + 8) * CP + ko + 2 * t4);
            ah[mt][2] = *(const uint32_t*)(Ah + (br + g    ) * CP + ko + 2 * t4 + 8);
            ah[mt][3] = *(const uint32_t*)(Ah + (br + g + 8) * CP + ko + 2 * t4 + 8);
            al[mt][0] = *(const uint32_t*)(Al + (br + g    ) * CP + ko + 2 * t4);
            al[mt][1] = *(const uint32_t*)(Al + (br + g + 8) * CP + ko + 2 * t4);
            al[mt][2] = *(const uint32_t*)(Al + (br + g    ) * CP + ko + 2 * t4 + 8);
            al[mt][3] = *(const uint32_t*)(Al + (br + g + 8) * CP + ko + 2 * t4 + 8);
        }
#pragma unroll
        for (int nt = 0; nt < 8; nt++) {
            const int bn = wn * 64 + nt * 8 + g;
            uint32_t bh[2], bl[2];
            bh[0] = *(const uint32_t*)(Bh + bn * CP + ko + 2 * t4);
            bh[1] = *(const uint32_t*)(Bh + bn * CP + ko + 2 * t4 + 8);
            bl[0] = *(const uint32_t*)(Bl + bn * CP + ko + 2 * t4);
            bl[1] = *(const uint32_t*)(Bl + bn * CP + ko + 2 * t4 + 8);
#pragma unroll
            for (int mt = 0; mt < 2; mt++) {
                mma_f16(acc[mt][nt], ah[mt], bh);
                mma_f16(acc[mt][nt], al[mt], bh);
                mma_f16(acc[mt][nt], ah[mt], bl);
            }
        }
    }
}

__global__ void __launch_bounds__(256) chunk_kernel()
{
    __half* Qh  = (__half*)sm_dyn;      // -> S planes -> Ktw planes
    __half* Ql  = Qh + CPL;
    __half* Kh  = Qh + 2 * CPL;
    __half* Kl  = Qh + 3 * CPL;
    __half* Vth = Qh + 4 * CPL;
    __half* Vtl = Qh + 5 * CPL;
    float* dpow = (float*)(Qh + 6 * CPL);

    const uint32_t uQh = smem_u32(Qh);
    const int tid = threadIdx.x;
    const int lane = tid & 31, wid = tid >> 5;
    const int wm = wid >> 1, wn = wid & 1;
    const int g = lane >> 2, t4 = lane & 3;
    const int b = blockIdx.x / NCn;
    const int c = blockIdx.x % NCn;
    const size_t base = ((size_t)b * Sn + (size_t)c * Cn) * Mn;

#pragma unroll
    for (int it = 0; it < 8; it++) {
        const int sid = tid + it * 256;
        const int u = sid >> 4, seg = sid & 15;
        const uint32_t dof = (u * CP + seg * 8) * 2;
        const size_t sof = base + (size_t)u * Mn + seg * 8;
        CPASYNC16(uQh + dof,               g_qh + sof);
        CPASYNC16(uQh + CPL * 2 + dof,     g_ql + sof);
        CPASYNC16(uQh + 2 * CPL * 2 + dof, g_kh + sof);
        CPASYNC16(uQh + 3 * CPL * 2 + dof, g_kl + sof);
    }
    CPCOMMIT();

    if (tid < 128) dpow[tid] = powf(DECAYF, (float)tid);

#pragma unroll
    for (int it = 0; it < 8; it++) {
        const int task = tid + it * 256;
        const int u = task & 127, i0 = (task >> 7) * 8;
        uint4 dh = *(const uint4*)(g_vh + base + (size_t)u * Mn + i0);
        uint4 dl = *(const uint4*)(g_vl + base + (size_t)u * Mn + i0);
        const __half* ph = (const __half*)&dh;
        const __half* pl = (const __half*)&dl;
#pragma unroll
        for (int j = 0; j < 8; j++) {
            Vth[(i0 + j) * CP + u] = ph[j];
            Vtl[(i0 + j) * CP + u] = pl[j];
        }
    }

    CPWAIT0();
    __syncthreads();

    float acc[2][8][4];
#pragma unroll
    for (int mt = 0; mt < 2; mt++)
#pragma unroll
        for (int nt = 0; nt < 8; nt++)
#pragma unroll
            for (int r = 0; r < 4; r++) acc[mt][nt][r] = 0.f;
    gemm_sm_f16(Qh, Ql, Kh, Kl, acc, wm, wn, g, t4);

#pragma unroll
    for (int mt = 0; mt < 2; mt++)
#pragma unroll
        for (int nt = 0; nt < 8; nt++)
#pragma unroll
            for (int r = 0; r < 4; r++) {
                const int t = wm * 32 + mt * 16 + g + ((r >= 2) ? 8 : 0);
                const int u = wn * 64 + nt * 8 + 2 * t4 + (r & 1);
                acc[mt][nt][r] = (u < t) ? acc[mt][nt][r] * (LRF * dpow[t - 1 - u]) : 0.f;
            }
    __syncthreads();

#pragma unroll
    for (int mt = 0; mt < 2; mt++) {
        const int r0 = wm * 32 + mt * 16 + g;
#pragma unroll
        for (int nt = 0; nt < 8; nt++) {
            const int c0 = wn * 64 + nt * 8 + 2 * t4;
            __half h0,l0,h1,l1;
            splith(acc[mt][nt][0], h0, l0); splith(acc[mt][nt][1], h1, l1);
            *(uint32_t*)(Qh + r0 * CP + c0) = packh2(h0, h1);
            *(uint32_t*)(Ql + r0 * CP + c0) = packh2(l0, l1);
            splith(acc[mt][nt][2], h0, l0); splith(acc[mt][nt][3], h1, l1);
            *(uint32_t*)(Qh + (r0 + 8) * CP + c0) = packh2(h0, h1);
            *(uint32_t*)(Ql + (r0 + 8) * CP + c0) = packh2(l0, l1);
        }
    }
    __syncthreads();

    float acc2[2][8][4];
#pragma unroll
    for (int mt = 0; mt < 2; mt++)
#pragma unroll
        for (int nt = 0; nt < 8; nt++)
#pragma unroll
            for (int r = 0; r < 4; r++) acc2[mt][nt][r] = 0.f;
    gemm_sm_f16(Qh, Ql, Vth, Vtl, acc2, wm, wn, g, t4);
#pragma unroll
    for (int mt = 0; mt < 2; mt++) {
        const int r0 = wm * 32 + mt * 16 + g;
#pragma unroll
        for (int nt = 0; nt < 8; nt++) {
            const int c0 = wn * 64 + nt * 8 + 2 * t4;
            *(float2*)(g_att + base + (size_t)r0 * Mn + c0)       = make_float2(acc2[mt][nt][0], acc2[mt][nt][1]);
            *(float2*)(g_att + base + (size_t)(r0 + 8) * Mn + c0) = make_float2(acc2[mt][nt][2], acc2[mt][nt][3]);
        }
    }
    __syncthreads();

#pragma unroll
    for (int it = 0; it < 8; it++) {
        const int task = tid + it * 256;
        const int u = task & 127, j0 = (task >> 7) * 8;
        const float w = LRF * dpow[127 - u];
#pragma unroll
        for (int j = 0; j < 8; j++) {
            float f = (__half2float(Kh[u * CP + j0 + j]) +
                       __half2float(Kl[u * CP + j0 + j])) * w;
            __half h, l; splith(f, h, l);
            Qh[(j0 + j) * CP + u] = h;
            Ql[(j0 + j) * CP + u] = l;
        }
    }
    __syncthreads();

    float acc3[2][8][4];
#pragma unroll
    for (int mt = 0; mt < 2; mt++)
#pragma unroll
        for (int nt = 0; nt < 8; nt++)
#pragma unroll
            for (int r = 0; r < 4; r++) acc3[mt][nt][r] = 0.f;
    gemm_sm_f16(Vth, Vtl, Qh, Ql, acc3, wm, wn, g, t4);

    const size_t dsbase = ((size_t)b * NCn + c) * (Mn * Mn);
#pragma unroll
    for (int mt = 0; mt < 2; mt++) {
        const int r0 = wm * 32 + mt * 16 + g;
#pragma unroll
        for (int nt = 0; nt < 8; nt++) {
            const int c0 = wn * 64 + nt * 8 + 2 * t4;
            *(float2*)(g_dS + dsbase + (size_t)r0 * Mn + c0)       = make_float2(acc3[mt][nt][0], acc3[mt][nt][1]);
            *(float2*)(g_dS + dsbase + (size_t)(r0 + 8) * Mn + c0) = make_float2(acc3[mt][nt][2], acc3[mt][nt][3]);
        }
    }
}

// ===========================================================================
// K3: prefix over chunks — float2/thread, 128 blocks, fully unrolled (MLP)
// ===========================================================================
__global__ void __launch_bounds__(256) scan_kernel(float* __restrict__ state_out)
{
    const int gg = blockIdx.x * blockDim.x + threadIdx.x;  // 0..32767
    const int b   = gg >> 13;
    const int ij0 = (gg & 8191) * 2;
    const float dc = powf(DECAYF, (float)Cn);
    float2 s = make_float2(0.f, 0.f);
#pragma unroll
    for (int c = 0; c < NCn; c++) {
        const size_t idx = ((size_t)b * NCn + c) * 16384 + ij0;
        float2 d = *(const float2*)(g_dS + idx);
        __half2 h = __floats2half2_rn(s.x, s.y);
        *(uint32_t*)(g_S16 + idx) = *(uint32_t*)&h;
        s.x = dc * s.x + d.x;
        s.y = dc * s.y + d.y;
    }
    *(float2*)(state_out + (size_t)b * 16384 + ij0) = s;
}

// ===========================================================================
extern "C" void kernel_launch(void* const* d_in, const int* in_sizes, int n_in,
                              void* d_out, int out_size)
{
    const float* x  = (const float*)d_in[0];
    const float* Wk = (const float*)d_in[1];
    const float* bk = (const float*)d_in[2];
    const float* Wv = (const float*)d_in[3];
    const float* bv = (const float*)d_in[4];
    const float* Wq = (const float*)d_in[5];
    const float* bq = (const float*)d_in[6];
    const float* Wo = (const float*)d_in[7];
    const float* bo = (const float*)d_in[8];

    float* y         = (float*)d_out;
    float* state_out = y + (size_t)BSn * Dn;

    const int PROJ_SMEM  = 6 * STGH * 2;                    // 36864
    const int FUSE_SMEM  = 8 * STGH * 2 + 128 * AP * 2;     // 83968
    const int CHUNK_SMEM = 6 * CPL * 2 + 512;               // 209408

    cudaFuncSetAttribute(proj_kernel,     cudaFuncAttributeMaxDynamicSharedMemorySize, PROJ_SMEM);
    cudaFuncSetAttribute(fuse_out_kernel, cudaFuncAttributeMaxDynamicSharedMemorySize, FUSE_SMEM);
    cudaFuncSetAttribute(chunk_kernel,    cudaFuncAttributeMaxDynamicSharedMemorySize, CHUNK_SMEM);

    conv_w_kernel<<<2048, 256>>>(Wk, Wv, Wq, Wo);
    proj_kernel<<<dim3(BSn / 128, 3), 256, PROJ_SMEM>>>(x, bk, bv, bq);
    chunk_kernel<<<Bn * NCn, 256, CHUNK_SMEM>>>();
    scan_kernel<<<128, 256>>>(state_out);
    fuse_out_kernel<<<Bn * NCn, 256, FUSE_SMEM>>>(bo, y);
}

// round 11
// speedup vs baseline: 1.7727x; 1.0801x over previous
#include <cuda_runtime.h>
#include <cuda_fp16.h>
#include <math.h>
#include <stdint.h>

// Problem constants
#define Bn   4
#define Sn   4096
#define Dn   1024
#define Mn   128
#define Cn   128
#define NCn  (Sn / Cn)
#define BSn  (Bn * Sn)
#define DECAYF 0.99f
#define LRF    0.01f

// Scratch (device globals)
__device__ __half g_kh[BSn * Mn], g_kl[BSn * Mn];
__device__ __half g_vh[BSn * Mn], g_vl[BSn * Mn];
__device__ __half g_qh[BSn * Mn], g_ql[BSn * Mn];
__device__ float  g_att[BSn * Mn];               // intra part only
__device__ float  g_dS [Bn * NCn * Mn * Mn];
__device__ __half g_S16[Bn * NCn * Mn * Mn];
__device__ __half g_W16[4 * 128 * 1024];         // Wk|Wv|Wq|Wo as f16

// ===========================================================================
// helpers
// ===========================================================================
__device__ __forceinline__ uint32_t smem_u32(const void* p) {
    uint32_t a;
    asm("{ .reg .u64 t; cvta.to.shared.u64 t, %1; cvt.u32.u64 %0, t; }"
        : "=r"(a) : "l"(p));
    return a;
}
__device__ __forceinline__ void splith(float v, __half& h, __half& l) {
    h = __float2half_rn(v);
    l = __float2half_rn(v - __half2float(h));
}
__device__ __forceinline__ uint32_t packh2(__half a, __half b) {
    __half2 t = __halves2half2(a, b);
    return *(uint32_t*)&t;
}
__device__ __forceinline__ void mma_f16(float* d, const uint32_t* a, const uint32_t* b) {
    asm volatile(
        "mma.sync.aligned.m16n8k16.row.col.f32.f16.f16.f32 "
        "{%0,%1,%2,%3}, {%4,%5,%6,%7}, {%8,%9}, {%0,%1,%2,%3};"
        : "+f"(d[0]), "+f"(d[1]), "+f"(d[2]), "+f"(d[3])
        : "r"(a[0]), "r"(a[1]), "r"(a[2]), "r"(a[3]), "r"(b[0]), "r"(b[1]));
}
#define CPASYNC16(sa, gp) \
    asm volatile("cp.async.ca.shared.global [%0], [%1], 16;" :: "r"(sa), "l"(gp))
#define CPCOMMIT() asm volatile("cp.async.commit_group;")
#define CPWAIT2()  asm volatile("cp.async.wait_group 2;")
#define CPWAIT1()  asm volatile("cp.async.wait_group 1;")
#define CPWAIT0()  asm volatile("cp.async.wait_group 0;")

extern __shared__ float sm_dyn[];

// ===========================================================================
// conv_w: weights -> f16
// ===========================================================================
__global__ void __launch_bounds__(256) conv_w_kernel(
    const float* __restrict__ Wk, const float* __restrict__ Wv,
    const float* __restrict__ Wq, const float* __restrict__ Wo)
{
    const int i = blockIdx.x * 256 + threadIdx.x;   // < 524288
    float v;
    if (i < 131072)       v = Wk[i];
    else if (i < 262144)  v = Wv[i - 131072];
    else if (i < 393216)  v = Wq[i - 262144];
    else                  v = Wo[i - 393216];
    g_W16[i] = __float2half_rn(v);
}

// ===========================================================================
// GEMM A-fp32 (proj): A fp32 reg-prefetch + cvt at staging, B f16 cp.async.
// 256 thr, 8 warps 4x2, warp tile 32x64, K-chunk 16. Outputs hi/lo planes.
// smem: sA[2][3072] + sB[4][3072] halves = 36864 B.
// ===========================================================================
#define SROWH 24
#define STGH  3072

__device__ __forceinline__ void gemm_proj(
    const float* __restrict__ A, int lda,
    const __half* __restrict__ Bm, int ldb, int K,
    const float* __restrict__ bias,
    __half* __restrict__ Ch, __half* __restrict__ Cl, int ldc)
{
    __half* sA = (__half*)sm_dyn;
    __half* sB = sA + 2 * STGH;
    const uint32_t sBu = smem_u32(sB);
    const int tid = threadIdx.x;
    const int lane = tid & 31, wid = tid >> 5;
    const int wm = wid >> 1, wn = wid & 1;
    const int g = lane >> 2, t4 = lane & 3;
    const int row = tid >> 1, half = tid & 1;

    float acc[2][8][4];
#pragma unroll
    for (int mt = 0; mt < 2; mt++)
#pragma unroll
        for (int nt = 0; nt < 8; nt++)
#pragma unroll
            for (int r = 0; r < 4; r++) acc[mt][nt][r] = 0.f;

    const int nc = K >> 4;

#define ISSUE_B(ch) do { \
    const uint32_t _d = (((ch) & 3) * STGH + row * SROWH + half * 8) * 2; \
    CPASYNC16(sBu + _d, Bm + (size_t)row * ldb + (ch) * 16 + half * 8); \
} while (0)

    ISSUE_B(0); CPCOMMIT();
    ISSUE_B(1); CPCOMMIT();
    ISSUE_B(2); CPCOMMIT();

    float pre[8];
    {
        const float* ap = A + (size_t)row * lda + half * 8;
        float4 a0 = *(const float4*)ap, a1 = *(const float4*)(ap + 4);
        pre[0]=a0.x; pre[1]=a0.y; pre[2]=a0.z; pre[3]=a0.w;
        pre[4]=a1.x; pre[5]=a1.y; pre[6]=a1.z; pre[7]=a1.w;
    }

    for (int ch = 0; ch < nc; ch++) {
        {
            uint32_t w[4];
#pragma unroll
            for (int j = 0; j < 4; j++) {
                __half2 h = __floats2half2_rn(pre[2*j], pre[2*j+1]);
                w[j] = *(uint32_t*)&h;
            }
            *(uint4*)(sA + (ch & 1) * STGH + row * SROWH + half * 8) = *(uint4*)w;
        }
        if (ch + 1 < nc) {
            const float* ap = A + (size_t)row * lda + (ch + 1) * 16 + half * 8;
            float4 a0 = *(const float4*)ap, a1 = *(const float4*)(ap + 4);
            pre[0]=a0.x; pre[1]=a0.y; pre[2]=a0.z; pre[3]=a0.w;
            pre[4]=a1.x; pre[5]=a1.y; pre[6]=a1.z; pre[7]=a1.w;
        }
        CPWAIT2();
        __syncthreads();
        if (ch + 3 < nc) ISSUE_B(ch + 3);
        CPCOMMIT();

        const __half* pA = sA + (ch & 1) * STGH;
        const __half* pB = sB + (ch & 3) * STGH;

        uint32_t af[2][4];
#pragma unroll
        for (int mt = 0; mt < 2; mt++) {
            const int br = wm * 32 + mt * 16;
            af[mt][0] = *(const uint32_t*)(pA + (br + g    ) * SROWH + 2 * t4);
            af[mt][1] = *(const uint32_t*)(pA + (br + g + 8) * SROWH + 2 * t4);
            af[mt][2] = *(const uint32_t*)(pA + (br + g    ) * SROWH + 2 * t4 + 8);
            af[mt][3] = *(const uint32_t*)(pA + (br + g + 8) * SROWH + 2 * t4 + 8);
        }
#pragma unroll
        for (int nt = 0; nt < 8; nt++) {
            const int bn = wn * 64 + nt * 8 + g;
            uint32_t bf[2];
            bf[0] = *(const uint32_t*)(pB + bn * SROWH + 2 * t4);
            bf[1] = *(const uint32_t*)(pB + bn * SROWH + 2 * t4 + 8);
            mma_f16(acc[0][nt], af[0], bf);
            mma_f16(acc[1][nt], af[1], bf);
        }
    }
#undef ISSUE_B

#pragma unroll
    for (int mt = 0; mt < 2; mt++) {
        const int r0 = wm * 32 + mt * 16 + g;
#pragma unroll
        for (int nt = 0; nt < 8; nt++) {
            const int c0 = wn * 64 + nt * 8 + 2 * t4;
            const float b0 = bias[c0], b1 = bias[c0 + 1];
            float v00 = acc[mt][nt][0] + b0, v01 = acc[mt][nt][1] + b1;
            float v10 = acc[mt][nt][2] + b0, v11 = acc[mt][nt][3] + b1;
            __half h0,l0,h1,l1;
            splith(v00, h0, l0); splith(v01, h1, l1);
            *(uint32_t*)(Ch + (size_t)r0 * ldc + c0) = packh2(h0, h1);
            *(uint32_t*)(Cl + (size_t)r0 * ldc + c0) = packh2(l0, l1);
            splith(v10, h0, l0); splith(v11, h1, l1);
            *(uint32_t*)(Ch + (size_t)(r0 + 8) * ldc + c0) = packh2(h0, h1);
            *(uint32_t*)(Cl + (size_t)(r0 + 8) * ldc + c0) = packh2(l0, l1);
        }
    }
}

// ===========================================================================
// K1: projections -> hi/lo planes   grid (128, 3)
// ===========================================================================
__global__ void __launch_bounds__(256, 2) proj_kernel(
    const float* __restrict__ x,
    const float* __restrict__ bk, const float* __restrict__ bv,
    const float* __restrict__ bq)
{
    const size_t rb = (size_t)blockIdx.x * 128;
    const int yv = blockIdx.y;
    const float* bias = (yv == 0) ? bk : (yv == 1) ? bv : bq;
    __half* Ch = (yv == 0) ? g_kh : (yv == 1) ? g_vh : g_qh;
    __half* Cl = (yv == 0) ? g_kl : (yv == 1) ? g_vl : g_ql;
    gemm_proj(x + rb * Dn, Dn, g_W16 + (size_t)yv * 131072, Dn, Dn,
              bias, Ch + rb * Mn, Cl + rb * Mn, Mn);
}

// ===========================================================================
// K4+K5 fused: per (b,c) block:
//   stage 1: inter = q x S^T (f16 cp.async), att_tile = g_att + decay^t*inter
//            -> fp16 smem tile
//   stage 2: y[128, 1024] = att_tile x Wo^T + bo, 8 full 128x128 Wo tiles in a
//            2-deep cp.async ring (256 MMAs per wait/sync pair)
// smem: ring 8*3072 halves (49152 B) + sAtt 128*136 (34816 B)
//       + sW 2x 128*136 (69632 B) = 153600 B
// ===========================================================================
#define AP 136
#define APL (128 * AP)

__global__ void __launch_bounds__(256) fuse_out_kernel(
    const float* __restrict__ bo, float* __restrict__ y)
{
    __half* sQ   = (__half*)sm_dyn;        // stage-1 A ring (4)
    __half* sS   = sQ + 4 * STGH;          // stage-1 B ring (4)
    __half* sAtt = sQ + 8 * STGH;          // 128 x AP
    __half* sW   = sAtt + APL;             // 2 x 128 x AP
    const uint32_t uQ = smem_u32(sQ), uS = smem_u32(sS), uW = smem_u32(sW);
    const int tid = threadIdx.x;
    const int lane = tid & 31, wid = tid >> 5;
    const int wm = wid >> 1, wn = wid & 1;
    const int g = lane >> 2, t4 = lane & 3;
    const int row = tid >> 1, half = tid & 1;

    const int b = blockIdx.x / NCn;
    const int c = blockIdx.x % NCn;
    const size_t base  = ((size_t)b * Sn + (size_t)c * Cn) * Mn;
    const size_t sbase = ((size_t)b * NCn + c) * 16384;
    const __half* Aq = g_qh + base;
    const __half* Bs = g_S16 + sbase;
    const __half* Wo = g_W16 + 393216;

    // ---------------- stage 1: inter GEMM ----------------
    float acc[2][8][4];
#pragma unroll
    for (int mt = 0; mt < 2; mt++)
#pragma unroll
        for (int nt = 0; nt < 8; nt++)
#pragma unroll
            for (int r = 0; r < 4; r++) acc[mt][nt][r] = 0.f;

#define ISSUE1(ch) do { \
    const uint32_t _d = (((ch) & 3) * STGH + row * SROWH + half * 8) * 2; \
    const size_t _s = (size_t)row * Mn + (ch) * 16 + half * 8; \
    CPASYNC16(uQ + _d, Aq + _s); \
    CPASYNC16(uS + _d, Bs + _s); \
} while (0)

    ISSUE1(0); CPCOMMIT();
    ISSUE1(1); CPCOMMIT();
    ISSUE1(2); CPCOMMIT();

    for (int ch = 0; ch < 8; ch++) {
        CPWAIT2();
        __syncthreads();
        if (ch + 3 < 8) ISSUE1(ch + 3);
        CPCOMMIT();

        const __half* pA = sQ + (ch & 3) * STGH;
        const __half* pB = sS + (ch & 3) * STGH;

        uint32_t af[2][4];
#pragma unroll
        for (int mt = 0; mt < 2; mt++) {
            const int br = wm * 32 + mt * 16;
            af[mt][0] = *(const uint32_t*)(pA + (br + g    ) * SROWH + 2 * t4);
            af[mt][1] = *(const uint32_t*)(pA + (br + g + 8) * SROWH + 2 * t4);
            af[mt][2] = *(const uint32_t*)(pA + (br + g    ) * SROWH + 2 * t4 + 8);
            af[mt][3] = *(const uint32_t*)(pA + (br + g + 8) * SROWH + 2 * t4 + 8);
        }
#pragma unroll
        for (int nt = 0; nt < 8; nt++) {
            const int bn = wn * 64 + nt * 8 + g;
            uint32_t bf[2];
            bf[0] = *(const uint32_t*)(pB + bn * SROWH + 2 * t4);
            bf[1] = *(const uint32_t*)(pB + bn * SROWH + 2 * t4 + 8);
            mma_f16(acc[0][nt], af[0], bf);
            mma_f16(acc[1][nt], af[1], bf);
        }
    }
#undef ISSUE1

    CPWAIT0();
    __syncthreads();

    // epilogue: att = intra (fp32) + decay^t * inter -> fp16 tile; then start
    // prefetching the first two Wo tiles.
#pragma unroll
    for (int mt = 0; mt < 2; mt++) {
        const int r0 = wm * 32 + mt * 16 + g;
        const float f0 = powf(DECAYF, (float)r0);
        const float f1 = powf(DECAYF, (float)(r0 + 8));
#pragma unroll
        for (int nt = 0; nt < 8; nt++) {
            const int c0 = wn * 64 + nt * 8 + 2 * t4;
            float2 i0v = *(const float2*)(g_att + base + (size_t)r0 * Mn + c0);
            float2 i1v = *(const float2*)(g_att + base + (size_t)(r0 + 8) * Mn + c0);
            __half2 h0 = __floats2half2_rn(i0v.x + f0 * acc[mt][nt][0],
                                           i0v.y + f0 * acc[mt][nt][1]);
            __half2 h1 = __floats2half2_rn(i1v.x + f1 * acc[mt][nt][2],
                                           i1v.y + f1 * acc[mt][nt][3]);
            *(uint32_t*)(sAtt + r0 * AP + c0)       = *(uint32_t*)&h0;
            *(uint32_t*)(sAtt + (r0 + 8) * AP + c0) = *(uint32_t*)&h1;
        }
    }

#define ISSUE_TILE(cb) do { \
    const uint32_t _bo = ((cb) & 1) * APL; \
    _Pragma("unroll") \
    for (int _it = 0; _it < 8; _it++) { \
        const int _sid = tid + _it * 256; \
        const int _u = _sid >> 4, _sg = _sid & 15; \
        CPASYNC16(uW + (_bo + _u * AP + _sg * 8) * 2, \
                  Wo + (size_t)((cb) * 128 + _u) * Mn + _sg * 8); \
    } \
} while (0)

    ISSUE_TILE(0); CPCOMMIT();
    ISSUE_TILE(1); CPCOMMIT();
    __syncthreads();   // sAtt visible to all warps

    // ---------------- stage 2: y = att x Wo^T + bo ----------------
    const size_t yrow = (size_t)b * Sn + (size_t)c * Cn;

    for (int cb = 0; cb < 8; cb++) {
        CPWAIT1();
        __syncthreads();
        const __half* pW = sW + (cb & 1) * APL;

        float acy[2][8][4];
#pragma unroll
        for (int mt = 0; mt < 2; mt++)
#pragma unroll
            for (int nt = 0; nt < 8; nt++)
#pragma unroll
                for (int r = 0; r < 4; r++) acy[mt][nt][r] = 0.f;

#pragma unroll
        for (int kc = 0; kc < 8; kc++) {
            const int ko = kc * 16;
            uint32_t af[2][4];
#pragma unroll
            for (int mt = 0; mt < 2; mt++) {
                const int br = wm * 32 + mt * 16;
                af[mt][0] = *(const uint32_t*)(sAtt + (br + g    ) * AP + ko + 2 * t4);
                af[mt][1] = *(const uint32_t*)(sAtt + (br + g + 8) * AP + ko + 2 * t4);
                af[mt][2] = *(const uint32_t*)(sAtt + (br + g    ) * AP + ko + 2 * t4 + 8);
                af[mt][3] = *(const uint32_t*)(sAtt + (br + g + 8) * AP + ko + 2 * t4 + 8);
            }
#pragma unroll
            for (int nt = 0; nt < 8; nt++) {
                const int bn = wn * 64 + nt * 8 + g;
                uint32_t bf[2];
                bf[0] = *(const uint32_t*)(pW + bn * AP + ko + 2 * t4);
                bf[1] = *(const uint32_t*)(pW + bn * AP + ko + 2 * t4 + 8);
                mma_f16(acy[0][nt], af[0], bf);
                mma_f16(acy[1][nt], af[1], bf);
            }
        }

#pragma unroll
        for (int mt = 0; mt < 2; mt++) {
            const int r0 = wm * 32 + mt * 16 + g;
#pragma unroll
            for (int nt = 0; nt < 8; nt++) {
                const int c0 = wn * 64 + nt * 8 + 2 * t4;
                const float b0 = bo[cb * 128 + c0], b1 = bo[cb * 128 + c0 + 1];
                *(float2*)(y + (yrow + r0) * Dn + cb * 128 + c0) =
                    make_float2(acy[mt][nt][0] + b0, acy[mt][nt][1] + b1);
                *(float2*)(y + (yrow + r0 + 8) * Dn + cb * 128 + c0) =
                    make_float2(acy[mt][nt][2] + b0, acy[mt][nt][3] + b1);
            }
        }
        __syncthreads();   // done reading sW[cb&1] before reuse
        if (cb + 2 < 8) { ISSUE_TILE(cb + 2); }
        CPCOMMIT();
    }
#undef ISSUE_TILE
}

// ===========================================================================
// K2: chunk — fp16 hi/lo 2-plane compensated, three 128^3 GEMMs on resident
// smem planes. grid 128, 256 thr. smem ~209.4 KB.
// ===========================================================================
#define CP 136
#define CPL (128 * CP)

__device__ __forceinline__ void gemm_sm_f16(
    const __half* __restrict__ Ah, const __half* __restrict__ Al,
    const __half* __restrict__ Bh, const __half* __restrict__ Bl,
    float acc[2][8][4], int wm, int wn, int g, int t4)
{
#pragma unroll
    for (int kk = 0; kk < 8; kk++) {
        const int ko = kk * 16;
        uint32_t ah[2][4], al[2][4];
#pragma unroll
        for (int mt = 0; mt < 2; mt++) {
            const int br = wm * 32 + mt * 16;
            ah[mt][0] = *(const uint32_t*)(Ah + (br + g    ) * CP + ko + 2 * t4);
            ah[mt][1] = *(const uint32_t*)(Ah + (br + g + 8) * CP + ko + 2 * t4);
            ah[mt][2] = *(const uint32_t*)(Ah + (br + g    ) * CP + ko + 2 * t4 + 8);
            ah[mt][3] = *(const uint32_t*)(Ah + (br + g + 8) * CP + ko + 2 * t4 + 8);
            al[mt][0] = *(const uint32_t*)(Al + (br + g    ) * CP + ko + 2 * t4);
            al[mt][1] = *(const uint32_t*)(Al + (br + g + 8) * CP + ko + 2 * t4);
            al[mt][2] = *(const uint32_t*)(Al + (br + g    ) * CP + ko + 2 * t4 + 8);
            al[mt][3] = *(const uint32_t*)(Al + (br + g + 8) * CP + ko + 2 * t4 + 8);
        }
#pragma unroll
        for (int nt = 0; nt < 8; nt++) {
            const int bn = wn * 64 + nt * 8 + g;
            uint32_t bh[2], bl[2];
            bh[0] = *(const uint32_t*)(Bh + bn * CP + ko + 2 * t4);
            bh[1] = *(const uint32_t*)(Bh + bn * CP + ko + 2 * t4 + 8);
            bl[0] = *(const uint32_t*)(Bl + bn * CP + ko + 2 * t4);
            bl[1] = *(const uint32_t*)(Bl + bn * CP + ko + 2 * t4 + 8);
#pragma unroll
            for (int mt = 0; mt < 2; mt++) {
                mma_f16(acc[mt][nt], ah[mt], bh);
                mma_f16(acc[mt][nt], al[mt], bh);
                mma_f16(acc[mt][nt], ah[mt], bl);
            }
        }
    }
}

__global__ void __launch_bounds__(256) chunk_kernel()
{
    __half* Qh  = (__half*)sm_dyn;      // -> S planes -> Ktw planes
    __half* Ql  = Qh + CPL;
    __half* Kh  = Qh + 2 * CPL;
    __half* Kl  = Qh + 3 * CPL;
    __half* Vth = Qh + 4 * CPL;
    __half* Vtl = Qh + 5 * CPL;
    float* dpow = (float*)(Qh + 6 * CPL);

    const uint32_t uQh = smem_u32(Qh);
    const int tid = threadIdx.x;
    const int lane = tid & 31, wid = tid >> 5;
    const int wm = wid >> 1, wn = wid & 1;
    const int g = lane >> 2, t4 = lane & 3;
    const int b = blockIdx.x / NCn;
    const int c = blockIdx.x % NCn;
    const size_t base = ((size_t)b * Sn + (size_t)c * Cn) * Mn;

#pragma unroll
    for (int it = 0; it < 8; it++) {
        const int sid = tid + it * 256;
        const int u = sid >> 4, seg = sid & 15;
        const uint32_t dof = (u * CP + seg * 8) * 2;
        const size_t sof = base + (size_t)u * Mn + seg * 8;
        CPASYNC16(uQh + dof,               g_qh + sof);
        CPASYNC16(uQh + CPL * 2 + dof,     g_ql + sof);
        CPASYNC16(uQh + 2 * CPL * 2 + dof, g_kh + sof);
        CPASYNC16(uQh + 3 * CPL * 2 + dof, g_kl + sof);
    }
    CPCOMMIT();

    if (tid < 128) dpow[tid] = powf(DECAYF, (float)tid);

#pragma unroll
    for (int it = 0; it < 8; it++) {
        const int task = tid + it * 256;
        const int u = task & 127, i0 = (task >> 7) * 8;
        uint4 dh = *(const uint4*)(g_vh + base + (size_t)u * Mn + i0);
        uint4 dl = *(const uint4*)(g_vl + base + (size_t)u * Mn + i0);
        const __half* ph = (const __half*)&dh;
        const __half* pl = (const __half*)&dl;
#pragma unroll
        for (int j = 0; j < 8; j++) {
            Vth[(i0 + j) * CP + u] = ph[j];
            Vtl[(i0 + j) * CP + u] = pl[j];
        }
    }

    CPWAIT0();
    __syncthreads();

    float acc[2][8][4];
#pragma unroll
    for (int mt = 0; mt < 2; mt++)
#pragma unroll
        for (int nt = 0; nt < 8; nt++)
#pragma unroll
            for (int r = 0; r < 4; r++) acc[mt][nt][r] = 0.f;
    gemm_sm_f16(Qh, Ql, Kh, Kl, acc, wm, wn, g, t4);

#pragma unroll
    for (int mt = 0; mt < 2; mt++)
#pragma unroll
        for (int nt = 0; nt < 8; nt++)
#pragma unroll
            for (int r = 0; r < 4; r++) {
                const int t = wm * 32 + mt * 16 + g + ((r >= 2) ? 8 : 0);
                const int u = wn * 64 + nt * 8 + 2 * t4 + (r & 1);
                acc[mt][nt][r] = (u < t) ? acc[mt][nt][r] * (LRF * dpow[t - 1 - u]) : 0.f;
            }
    __syncthreads();

#pragma unroll
    for (int mt = 0; mt < 2; mt++) {
        const int r0 = wm * 32 + mt * 16 + g;
#pragma unroll
        for (int nt = 0; nt < 8; nt++) {
            const int c0 = wn * 64 + nt * 8 + 2 * t4;
            __half h0,l0,h1,l1;
            splith(acc[mt][nt][0], h0, l0); splith(acc[mt][nt][1], h1, l1);
            *(uint32_t*)(Qh + r0 * CP + c0) = packh2(h0, h1);
            *(uint32_t*)(Ql + r0 * CP + c0) = packh2(l0, l1);
            splith(acc[mt][nt][2], h0, l0); splith(acc[mt][nt][3], h1, l1);
            *(uint32_t*)(Qh + (r0 + 8) * CP + c0) = packh2(h0, h1);
            *(uint32_t*)(Ql + (r0 + 8) * CP + c0) = packh2(l0, l1);
        }
    }
    __syncthreads();

    float acc2[2][8][4];
#pragma unroll
    for (int mt = 0; mt < 2; mt++)
#pragma unroll
        for (int nt = 0; nt < 8; nt++)
#pragma unroll
            for (int r = 0; r < 4; r++) acc2[mt][nt][r] = 0.f;
    gemm_sm_f16(Qh, Ql, Vth, Vtl, acc2, wm, wn, g, t4);
#pragma unroll
    for (int mt = 0; mt < 2; mt++) {
        const int r0 = wm * 32 + mt * 16 + g;
#pragma unroll
        for (int nt = 0; nt < 8; nt++) {
            const int c0 = wn * 64 + nt * 8 + 2 * t4;
            *(float2*)(g_att + base + (size_t)r0 * Mn + c0)       = make_float2(acc2[mt][nt][0], acc2[mt][nt][1]);
            *(float2*)(g_att + base + (size_t)(r0 + 8) * Mn + c0) = make_float2(acc2[mt][nt][2], acc2[mt][nt][3]);
        }
    }
    __syncthreads();

#pragma unroll
    for (int it = 0; it < 8; it++) {
        const int task = tid + it * 256;
        const int u = task & 127, j0 = (task >> 7) * 8;
        const float w = LRF * dpow[127 - u];
#pragma unroll
        for (int j = 0; j < 8; j++) {
            float f = (__half2float(Kh[u * CP + j0 + j]) +
                       __half2float(Kl[u * CP + j0 + j])) * w;
            __half h, l; splith(f, h, l);
            Qh[(j0 + j) * CP + u] = h;
            Ql[(j0 + j) * CP + u] = l;
        }
    }
    __syncthreads();

    float acc3[2][8][4];
#pragma unroll
    for (int mt = 0; mt < 2; mt++)
#pragma unroll
        for (int nt = 0; nt < 8; nt++)
#pragma unroll
            for (int r = 0; r < 4; r++) acc3[mt][nt][r] = 0.f;
    gemm_sm_f16(Vth, Vtl, Qh, Ql, acc3, wm, wn, g, t4);

    const size_t dsbase = ((size_t)b * NCn + c) * (Mn * Mn);
#pragma unroll
    for (int mt = 0; mt < 2; mt++) {
        const int r0 = wm * 32 + mt * 16 + g;
#pragma unroll
        for (int nt = 0; nt < 8; nt++) {
            const int c0 = wn * 64 + nt * 8 + 2 * t4;
            *(float2*)(g_dS + dsbase + (size_t)r0 * Mn + c0)       = make_float2(acc3[mt][nt][0], acc3[mt][nt][1]);
            *(float2*)(g_dS + dsbase + (size_t)(r0 + 8) * Mn + c0) = make_float2(acc3[mt][nt][2], acc3[mt][nt][3]);
        }
    }
}

// ===========================================================================
// K3: tile-parallel two-level scan over chunks.
// grid 1024 blocks (4 b x 256 ij-tiles of 64), 256 threads.
// Each block: bulk-load dS tile [32 x 64] (MLP-heavy), segment scans in
// registers (8 chunks/thread), 4-segment carry combine, write S16 + state.
// ===========================================================================
__global__ void __launch_bounds__(256) scan_kernel(float* __restrict__ state_out)
{
    __shared__ float t[32][64];
    __shared__ float seg[4][64];
    __shared__ float carr[4][64];

    const int tid = threadIdx.x;
    const int b   = blockIdx.x >> 8;
    const int ij0 = (blockIdx.x & 255) * 64;
    const float dc  = powf(DECAYF, (float)Cn);
    const float dc8 = powf(dc, 8.0f);

    // bulk load: 8 independent loads per thread, coalesced per chunk-row
#pragma unroll
    for (int it = 0; it < 8; it++) {
        const int idx = tid + it * 256;          // 0..2047
        const int cc = idx >> 6, j = idx & 63;
        t[cc][j] = g_dS[((size_t)b * NCn + cc) * 16384 + ij0 + j];
    }
    __syncthreads();

    const int q = tid >> 6, j = tid & 63;

    // phase A: segment inclusive sums
    {
        float r = 0.f;
#pragma unroll
        for (int i = 0; i < 8; i++) r = dc * r + t[q * 8 + i][j];
        seg[q][j] = r;
    }
    __syncthreads();

    // phase B: carries (threads 0..63)
    if (tid < 64) {
        float csum = 0.f;
#pragma unroll
        for (int qq = 0; qq < 4; qq++) {
            carr[qq][tid] = csum;
            csum = dc8 * csum + seg[qq][tid];
        }
        state_out[(size_t)b * 16384 + ij0 + tid] = csum;
    }
    __syncthreads();

    // phase C: exclusive prefixes + S16 stores
    {
        float r = carr[q][j];
#pragma unroll
        for (int i = 0; i < 8; i++) {
            const int cc = q * 8 + i;
            g_S16[((size_t)b * NCn + cc) * 16384 + ij0 + j] = __float2half_rn(r);
            r = dc * r + t[cc][j];
        }
    }
}

// ===========================================================================
extern "C" void kernel_launch(void* const* d_in, const int* in_sizes, int n_in,
                              void* d_out, int out_size)
{
    const float* x  = (const float*)d_in[0];
    const float* Wk = (const float*)d_in[1];
    const float* bk = (const float*)d_in[2];
    const float* Wv = (const float*)d_in[3];
    const float* bv = (const float*)d_in[4];
    const float* Wq = (const float*)d_in[5];
    const float* bq = (const float*)d_in[6];
    const float* Wo = (const float*)d_in[7];
    const float* bo = (const float*)d_in[8];

    float* y         = (float*)d_out;
    float* state_out = y + (size_t)BSn * Dn;

    const int PROJ_SMEM  = 6 * STGH * 2;                      // 36864
    const int FUSE_SMEM  = (8 * STGH + 3 * APL) * 2;          // 153600
    const int CHUNK_SMEM = 6 * CPL * 2 + 512;                 // 209408

    cudaFuncSetAttribute(proj_kernel,     cudaFuncAttributeMaxDynamicSharedMemorySize, PROJ_SMEM);
    cudaFuncSetAttribute(fuse_out_kernel, cudaFuncAttributeMaxDynamicSharedMemorySize, FUSE_SMEM);
    cudaFuncSetAttribute(chunk_kernel,    cudaFuncAttributeMaxDynamicSharedMemorySize, CHUNK_SMEM);

    conv_w_kernel<<<2048, 256>>>(Wk, Wv, Wq, Wo);
    proj_kernel<<<dim3(BSn / 128, 3), 256, PROJ_SMEM>>>(x, bk, bv, bq);
    chunk_kernel<<<Bn * NCn, 256, CHUNK_SMEM>>>();
    scan_kernel<<<Bn * 256, 256>>>(state_out);
    fuse_out_kernel<<<Bn * NCn, 256, FUSE_SMEM>>>(bo, y);
}